// round 3
// baseline (speedup 1.0000x reference)
#include <cuda_runtime.h>
#include <math.h>
#include <stdint.h>

#define Bb 8
#define Nn 1024
#define Ee 256
#define Hh 4
#define Uu 6
#define Oo 8
#define LAMBDA_INIT 0.63212055882855767840f

typedef unsigned long long ull;

// ---------------- scratch (static device memory; no allocation) ----------------
__device__ unsigned char g_maskT[(size_t)Bb * Nn * Nn];          // 8 MB
__device__ float g_v[(size_t)Bb * Nn * Ee];                      // 8 MB  v[b][n][h*64+d]
__device__ float g_outpre[(size_t)Bb * Nn * Ee];                 // 8 MB
__device__ float g_l[(size_t)Bb * Oo * Nn];                      // softmax denominators
__device__ float g_beta;
__device__ int   g_mask_kind;                                    // 0=u8, 1=i32, 2=f32

// ---------------- f32x2 helpers ----------------
__device__ __forceinline__ ull pack2(float a, float b) {
    ull r;
    asm("mov.b64 %0, {%1,%2};" : "=l"(r) : "f"(a), "f"(b));
    return r;
}
__device__ __forceinline__ float2 unpack2(ull v) {
    float2 r;
    asm("mov.b64 {%0,%1}, %2;" : "=f"(r.x), "=f"(r.y) : "l"(v));
    return r;
}
__device__ __forceinline__ ull ffma2(ull a, ull b, ull c) {
    ull d;
    asm("fma.rn.f32x2 %0, %1, %2, %3;" : "=l"(d) : "l"(a), "l"(b), "l"(c));
    return d;
}

// ---------------- K0: beta ----------------
__global__ void beta_kernel(const float* __restrict__ lq, const float* __restrict__ lk,
                            float* __restrict__ beta_slot) {
    __shared__ float red[128];
    int t = threadIdx.x;
    float s = (t < 100) ? lq[t] * lk[t] : 0.f;
    red[t] = s;
    __syncthreads();
    for (int st = 64; st > 0; st >>= 1) {
        if (t < st) red[t] += red[t + st];
        __syncthreads();
    }
    if (t == 0) {
        float lam1 = expf(red[0]);
        float z = lam1 * LAMBDA_INIT;
        float beta = 1.f / (1.f + expf(-z));
        g_beta = beta;
        *beta_slot = beta;
    }
}

// ---------------- K1: mask dtype sniffer ----------------
__global__ void detect_kernel(const unsigned char* __restrict__ raw) {
    __shared__ int cnt[4];
    if (threadIdx.x < 4) cnt[threadIdx.x] = 0;
    __syncthreads();
    for (int i = threadIdx.x; i < 16384; i += blockDim.x)
        if (raw[i]) atomicAdd(&cnt[i & 3], 1);
    __syncthreads();
    if (threadIdx.x == 0) {
        int kind;
        if (cnt[1] == 0 && cnt[2] == 0 && cnt[3] == 0) kind = 1;       // int32
        else if (cnt[0] == 0 && cnt[1] == 0)           kind = 2;       // float32
        else                                            kind = 0;       // bytes
        g_mask_kind = kind;
    }
}

// ---------------- K2: mask transpose  maskT[b][i][j] = (umask[b][j][i] != 0) ----------------
__global__ void mask_transpose_kernel(const void* __restrict__ rawv) {
    __shared__ unsigned char tile[32][33];
    int b = blockIdx.z;
    int i0 = blockIdx.x * 32, j0 = blockIdx.y * 32;
    int tx = threadIdx.x, ty = threadIdx.y;
    int kind = g_mask_kind;
    size_t src = ((size_t)b * Nn + (j0 + ty)) * Nn + (i0 + tx);
    unsigned char v;
    if (kind == 0)      v = (((const unsigned char*)rawv)[src] != 0);
    else if (kind == 1) v = (((const int*)rawv)[src] != 0);
    else                v = (((const float*)rawv)[src] != 0.f);
    tile[ty][tx] = v;
    __syncthreads();
    g_maskT[((size_t)b * Nn + (i0 + ty)) * Nn + (j0 + tx)] = tile[tx][ty];
}

// ---------------- gemm: Y[row,f] = sum_e X[row,e] * W[f,e]  (rows=8192, E=256) ----------------
// 64x128 tile, 256 threads, 32 outputs/thread (8 rows x 4 cols)
__global__ __launch_bounds__(256) void gemm_xw_kernel(const float* __restrict__ X,
                                                      const float* __restrict__ W,
                                                      float* __restrict__ Y) {
    __shared__ float As[64][65];    // [row][k]
    __shared__ float Bs[64][132];   // [k][col]
    int t = threadIdx.x;
    int row0 = blockIdx.x * 64;
    int col0 = blockIdx.y * 128;
    int cg = t & 31;     // col = cg*4
    int rg = t >> 5;     // rows rg*8 .. +7  (warp-uniform)
    ull acc[8][2];
#pragma unroll
    for (int r = 0; r < 8; r++) { acc[r][0] = 0ULL; acc[r][1] = 0ULL; }

    for (int k0 = 0; k0 < Ee; k0 += 64) {
#pragma unroll
        for (int q = 0; q < 4; q++) {           // X tile 64x64
            int idx = t + q * 256;
            int r = idx >> 4, e4 = (idx & 15) * 4;
            float4 v = *(const float4*)(X + (size_t)(row0 + r) * Ee + k0 + e4);
            As[r][e4 + 0] = v.x; As[r][e4 + 1] = v.y; As[r][e4 + 2] = v.z; As[r][e4 + 3] = v.w;
        }
#pragma unroll
        for (int q = 0; q < 8; q++) {           // W tile 128f x 64e, transposed
            int idx = t + q * 256;
            int f = idx >> 4, e4 = (idx & 15) * 4;
            float4 v = *(const float4*)(W + (size_t)(col0 + f) * Ee + k0 + e4);
            Bs[e4 + 0][f] = v.x; Bs[e4 + 1][f] = v.y; Bs[e4 + 2][f] = v.z; Bs[e4 + 3][f] = v.w;
        }
        __syncthreads();
#pragma unroll 4
        for (int k = 0; k < 64; k++) {
            float4 bv = *(const float4*)&Bs[k][cg * 4];
            ull blo = pack2(bv.x, bv.y);
            ull bhi = pack2(bv.z, bv.w);
#pragma unroll
            for (int r = 0; r < 8; r++) {
                float a = As[rg * 8 + r][k];
                ull a2 = pack2(a, a);
                acc[r][0] = ffma2(a2, blo, acc[r][0]);
                acc[r][1] = ffma2(a2, bhi, acc[r][1]);
            }
        }
        __syncthreads();
    }
#pragma unroll
    for (int r = 0; r < 8; r++) {
        float2 lo = unpack2(acc[r][0]);
        float2 hi = unpack2(acc[r][1]);
        *(float4*)(Y + (size_t)(row0 + rg * 8 + r) * Ee + col0 + cg * 4) =
            make_float4(lo.x, lo.y, hi.x, hi.y);
    }
}

// ---------------- K4: softmax denominator l[b,o,i] = sum_j exp(score) ----------------
__global__ __launch_bounds__(256) void stats_kernel(const float* __restrict__ u,
                                                    const float* __restrict__ u_w,
                                                    const float* __restrict__ u_b) {
    int i = blockIdx.x, b = blockIdx.y, t = threadIdx.x;
    __shared__ ull s_w2[48];
    __shared__ ull s_b2[8];
    __shared__ float s_red[8][9];
    if (t < 48) { float w = u_w[t]; s_w2[t] = pack2(w, w); }
    if (t < 8)  { float bb = u_b[t]; s_b2[t] = pack2(bb, bb); }
    __syncthreads();

    int j0 = t * 4;
    unsigned mword = *(const unsigned*)(g_maskT + ((size_t)b * Nn + i) * Nn + j0);
    bool m0 = (mword & 0xFFu) != 0, m1 = ((mword >> 8) & 0xFFu) != 0;
    bool m2 = ((mword >> 16) & 0xFFu) != 0, m3 = ((mword >> 24) & 0xFFu) != 0;

    ulonglong2 u2[Uu];
#pragma unroll
    for (int c = 0; c < Uu; c++)
        u2[c] = *(const ulonglong2*)(u + ((size_t)(b * Uu + c) * Nn + i) * Nn + j0);

    float l[Oo];
#pragma unroll
    for (int o = 0; o < Oo; o++) {
        ull sa = s_b2[o], sb = s_b2[o];
#pragma unroll
        for (int c = 0; c < Uu; c++) {
            sa = ffma2(s_w2[o * Uu + c], u2[c].x, sa);
            sb = ffma2(s_w2[o * Uu + c], u2[c].y, sb);
        }
        float2 f0 = unpack2(sa), f1 = unpack2(sb);
        float acc = 0.f;
        if (!m0) acc += __expf(f0.x);
        if (!m1) acc += __expf(f0.y);
        if (!m2) acc += __expf(f1.x);
        if (!m3) acc += __expf(f1.y);
        l[o] = acc;
    }
#pragma unroll
    for (int o = 0; o < Oo; o++)
#pragma unroll
        for (int st = 16; st > 0; st >>= 1)
            l[o] += __shfl_xor_sync(0xFFFFFFFFu, l[o], st);
    int w = t >> 5, lane = t & 31;
    if (lane == 0) {
#pragma unroll
        for (int o = 0; o < Oo; o++) s_red[o][w] = l[o];
    }
    __syncthreads();
    if (t < 8) {
        float s = 0.f;
#pragma unroll
        for (int w2 = 0; w2 < 8; w2++) s += s_red[t][w2];
        g_l[((size_t)b * Oo + t) * Nn + i] = s;
    }
}

// ---------------- K5: fused attn_w compute + write + (attn_w @ v) accumulate ----------------
// block = (b, 32-row i strip), 512 threads, 2 blocks/SM, loop over 16 j-tiles of 64.
#define SM_W2   0        // 96 floats (48 ull)
#define SM_B2   96       // 16 floats (8 ull)
#define SM_BETA 112      // 16 floats (pad)
#define SM_RL   128      // 256 floats (8 o x 32 i)
#define SM_AS   384      // 256 rows x 33 = 8448 floats (j-major, col = i)
#define SM_VS   8832     // 64 x 256 = 16384 floats
#define SM_TOT  25216    // floats -> 100864 bytes

__global__ __launch_bounds__(512, 2) void fused_kernel(const float* __restrict__ u,
                                                       const float* __restrict__ u_w,
                                                       const float* __restrict__ u_b,
                                                       float* __restrict__ attn_out) {
    extern __shared__ float sm[];
    ull*   s_w2   = (ull*)(sm + SM_W2);
    ull*   s_b2   = (ull*)(sm + SM_B2);
    float* s_beta = sm + SM_BETA;
    float* s_rl   = sm + SM_RL;
    float* As     = sm + SM_AS;    // [h*64 + j][33] row = j-major, col = i
    float* Vs     = sm + SM_VS;    // [j][256]

    int t = threadIdx.x;
    int b = blockIdx.y;
    int i0 = blockIdx.x * 32;

    if (t < 48)      { float w = u_w[t]; s_w2[t] = pack2(w, w); }
    else if (t < 56) { float bb = u_b[t - 48]; s_b2[t - 48] = pack2(bb, bb); }
    else if (t == 56) *s_beta = g_beta;
    if (t < 256) {
        int o = t >> 5, il = t & 31;
        s_rl[t] = 1.0f / g_l[((size_t)b * Oo + o) * Nn + i0 + il];
    }
    __syncthreads();

    // phase A mapping: 1 row x 4 j per thread
    const int jq = t & 15, il = t >> 4;        // il 0..31
    // phase B mapping: 1 row x 16 d per thread
    const int ig = t & 31, dg = t >> 5;        // dg 0..15
    const int d0 = dg * 16;
    const int h_b = dg >> 2;
    const float beta = *s_beta;
    const int gi_a = i0 + il;

    ull acc[8];
#pragma unroll
    for (int k = 0; k < 8; k++) acc[k] = 0ULL;

    for (int jt0 = 0; jt0 < Nn; jt0 += 64) {
        // ---- load V tile [64][256] (completes during phase A) ----
#pragma unroll
        for (int q = 0; q < 8; q++) {
            int idx = t + q * 512;
            int r = idx >> 6, c = (idx & 63) * 4;
            *(float4*)&Vs[r * 256 + c] =
                *(const float4*)(g_v + ((size_t)b * Nn + jt0 + r) * Ee + c);
        }
        // ---- phase A: compute attn tile, write gmem + smem ----
        {
            int j0 = jt0 + jq * 4;
            unsigned mword = *(const unsigned*)(g_maskT + ((size_t)b * Nn + gi_a) * Nn + j0);
            bool m0 = (mword & 0xFFu) != 0, m1 = ((mword >> 8) & 0xFFu) != 0;
            bool m2 = ((mword >> 16) & 0xFFu) != 0, m3 = ((mword >> 24) & 0xFFu) != 0;
            ulonglong2 u2[Uu];
#pragma unroll
            for (int c = 0; c < Uu; c++)
                u2[c] = *(const ulonglong2*)(u + ((size_t)(b * Uu + c) * Nn + gi_a) * Nn + j0);
            int jb = jq * 4;
#pragma unroll
            for (int h = 0; h < Hh; h++) {
                int o0 = 2 * h, o1 = 2 * h + 1;
                ull sa0 = s_b2[o0], sb0 = s_b2[o0];
                ull sa1 = s_b2[o1], sb1 = s_b2[o1];
#pragma unroll
                for (int c = 0; c < Uu; c++) {
                    sa0 = ffma2(s_w2[o0 * Uu + c], u2[c].x, sa0);
                    sb0 = ffma2(s_w2[o0 * Uu + c], u2[c].y, sb0);
                    sa1 = ffma2(s_w2[o1 * Uu + c], u2[c].x, sa1);
                    sb1 = ffma2(s_w2[o1 * Uu + c], u2[c].y, sb1);
                }
                float2 f00 = unpack2(sa0), f01 = unpack2(sb0);
                float2 f10 = unpack2(sa1), f11 = unpack2(sb1);
                float rl0 = s_rl[o0 * 32 + il];
                float rl1 = s_rl[o1 * 32 + il];
                float p00 = m0 ? 0.f : __expf(f00.x) * rl0;
                float p01 = m1 ? 0.f : __expf(f00.y) * rl0;
                float p02 = m2 ? 0.f : __expf(f01.x) * rl0;
                float p03 = m3 ? 0.f : __expf(f01.y) * rl0;
                float p10 = m0 ? 0.f : __expf(f10.x) * rl1;
                float p11 = m1 ? 0.f : __expf(f10.y) * rl1;
                float p12 = m2 ? 0.f : __expf(f11.x) * rl1;
                float p13 = m3 ? 0.f : __expf(f11.y) * rl1;
                float a0 = p00 - beta * p10;
                float a1 = p01 - beta * p11;
                float a2 = p02 - beta * p12;
                float a3 = p03 - beta * p13;
                *(float4*)(attn_out + ((size_t)(b * Hh + h) * Nn + gi_a) * Nn + j0) =
                    make_float4(a0, a1, a2, a3);
                As[(h * 64 + jb + 0) * 33 + il] = a0;
                As[(h * 64 + jb + 1) * 33 + il] = a1;
                As[(h * 64 + jb + 2) * 33 + il] = a2;
                As[(h * 64 + jb + 3) * 33 + il] = a3;
            }
        }
        __syncthreads();
        // ---- phase B: acc += As(h_b) @ Vs ----
#pragma unroll 4
        for (int j = 0; j < 64; j++) {
            const ulonglong2* vp = (const ulonglong2*)&Vs[j * 256 + d0];
            ulonglong2 va = vp[0], vb = vp[1], vc = vp[2], vd = vp[3];
            float a = As[(h_b * 64 + j) * 33 + ig];
            ull a2 = pack2(a, a);
            acc[0] = ffma2(a2, va.x, acc[0]); acc[1] = ffma2(a2, va.y, acc[1]);
            acc[2] = ffma2(a2, vb.x, acc[2]); acc[3] = ffma2(a2, vb.y, acc[3]);
            acc[4] = ffma2(a2, vc.x, acc[4]); acc[5] = ffma2(a2, vc.y, acc[5]);
            acc[6] = ffma2(a2, vd.x, acc[6]); acc[7] = ffma2(a2, vd.y, acc[7]);
        }
        __syncthreads();
    }
    // epilogue: write out_pre[b][i0+ig][d0..d0+15]
    {
        float* op = g_outpre + ((size_t)b * Nn + i0 + ig) * Ee + d0;
#pragma unroll
        for (int k4 = 0; k4 < 4; k4++) {
            ulonglong2 st;
            st.x = acc[2 * k4]; st.y = acc[2 * k4 + 1];
            *(ulonglong2*)(op + k4 * 4) = st;
        }
    }
}

// ---------------- launch ----------------
extern "C" void kernel_launch(void* const* d_in, const int* in_sizes, int n_in,
                              void* d_out, int out_size) {
    const float* x     = (const float*)d_in[0];
    const float* u     = (const float*)d_in[1];
    const void*  umask = d_in[2];
    const float* v_w   = (const float*)d_in[3];
    const float* out_w = (const float*)d_in[4];
    const float* u_w   = (const float*)d_in[5];
    const float* u_b   = (const float*)d_in[6];
    const float* lq    = (const float*)d_in[7];
    const float* lk    = (const float*)d_in[8];

    float* out = (float*)d_out;
    const size_t OUT_ELEMS  = (size_t)Bb * Nn * Ee;          // 2097152
    const size_t ATTN_ELEMS = (size_t)Bb * Hh * Nn * Nn;     // 33554432
    float* attn_out  = out + OUT_ELEMS;
    float* beta_slot = out + OUT_ELEMS + ATTN_ELEMS;

    float* vptr = nullptr;
    float* optr = nullptr;
    cudaGetSymbolAddress((void**)&vptr, g_v);
    cudaGetSymbolAddress((void**)&optr, g_outpre);

    static bool attr_set = false;
    if (!attr_set) {
        cudaFuncSetAttribute(fused_kernel, cudaFuncAttributeMaxDynamicSharedMemorySize,
                             SM_TOT * 4);
        attr_set = true;
    }

    beta_kernel<<<1, 128>>>(lq, lk, beta_slot);
    detect_kernel<<<1, 256>>>((const unsigned char*)umask);
    mask_transpose_kernel<<<dim3(32, 32, 8), dim3(32, 32)>>>(umask);
    gemm_xw_kernel<<<dim3(128, 2), 256>>>(x, v_w, vptr);                // v projection
    stats_kernel<<<dim3(Nn, Bb), 256>>>(u, u_w, u_b);
    fused_kernel<<<dim3(32, 8), 512, SM_TOT * 4>>>(u, u_w, u_b, attn_out);
    gemm_xw_kernel<<<dim3(128, 2), 256>>>(optr, out_w, out);            // output projection
    (void)in_sizes; (void)n_in; (void)out_size;
}

// round 5
// speedup vs baseline: 1.2052x; 1.2052x over previous
#include <cuda_runtime.h>
#include <cuda_bf16.h>
#include <math.h>
#include <stdint.h>

#define Bb 8
#define Nn 1024
#define Ee 256
#define Hh 4
#define Uu 6
#define Oo 8
#define LAMBDA_INIT 0.63212055882855767840f

typedef unsigned long long ull;

// ---------------- scratch (static device memory; no allocation) ----------------
__device__ unsigned char g_maskT[(size_t)Bb * Nn * Nn];            // 8 MB
__device__ __nv_bfloat16 g_v_hi[(size_t)Bb * Nn * Ee];             // 4 MB  [b][n][e]
__device__ __nv_bfloat16 g_v_lo[(size_t)Bb * Nn * Ee];             // 4 MB
__device__ float g_outpre[(size_t)Bb * Nn * Ee];                   // 8 MB
__device__ float g_l[(size_t)Bb * Oo * Nn];                        // softmax denominators
__device__ float g_beta;
__device__ int   g_mask_kind;                                      // 0=u8, 1=i32, 2=f32

// ---------------- f32x2 helpers ----------------
__device__ __forceinline__ ull pack2(float a, float b) {
    ull r; asm("mov.b64 %0, {%1,%2};" : "=l"(r) : "f"(a), "f"(b)); return r;
}
__device__ __forceinline__ float2 unpack2(ull v) {
    float2 r; asm("mov.b64 {%0,%1}, %2;" : "=f"(r.x), "=f"(r.y) : "l"(v)); return r;
}
__device__ __forceinline__ ull ffma2(ull a, ull b, ull c) {
    ull d; asm("fma.rn.f32x2 %0, %1, %2, %3;" : "=l"(d) : "l"(a), "l"(b), "l"(c)); return d;
}
// packed bf16x2: lo16 = bf16(a0), hi16 = bf16(a1)
__device__ __forceinline__ uint32_t cvt_bf16x2(float a1, float a0) {
    uint32_t r; asm("cvt.rn.bf16x2.f32 %0, %1, %2;" : "=r"(r) : "f"(a1), "f"(a0)); return r;
}
__device__ __forceinline__ uint32_t smem_u32(const void* p) {
    uint32_t a;
    asm("{ .reg .u64 t; cvta.to.shared.u64 t, %1; cvt.u32.u64 %0, t; }" : "=r"(a) : "l"(p));
    return a;
}
__device__ __forceinline__ void ldmatrix_x4(uint32_t& r0, uint32_t& r1, uint32_t& r2,
                                            uint32_t& r3, uint32_t addr) {
    asm volatile("ldmatrix.sync.aligned.m8n8.x4.shared.b16 {%0,%1,%2,%3}, [%4];"
                 : "=r"(r0), "=r"(r1), "=r"(r2), "=r"(r3) : "r"(addr));
}
__device__ __forceinline__ void ldmatrix_x4_trans(uint32_t& r0, uint32_t& r1, uint32_t& r2,
                                                  uint32_t& r3, uint32_t addr) {
    asm volatile("ldmatrix.sync.aligned.m8n8.x4.trans.shared.b16 {%0,%1,%2,%3}, [%4];"
                 : "=r"(r0), "=r"(r1), "=r"(r2), "=r"(r3) : "r"(addr));
}
__device__ __forceinline__ void mma_bf16(float* c, uint32_t a0, uint32_t a1, uint32_t a2,
                                         uint32_t a3, uint32_t b0, uint32_t b1) {
    asm volatile(
        "mma.sync.aligned.m16n8k16.row.col.f32.bf16.bf16.f32 "
        "{%0,%1,%2,%3}, {%4,%5,%6,%7}, {%8,%9}, {%0,%1,%2,%3};"
        : "+f"(c[0]), "+f"(c[1]), "+f"(c[2]), "+f"(c[3])
        : "r"(a0), "r"(a1), "r"(a2), "r"(a3), "r"(b0), "r"(b1));
}

// ---------------- K0: beta ----------------
__global__ void beta_kernel(const float* __restrict__ lq, const float* __restrict__ lk,
                            float* __restrict__ beta_slot) {
    __shared__ float red[128];
    int t = threadIdx.x;
    red[t] = (t < 100) ? lq[t] * lk[t] : 0.f;
    __syncthreads();
    for (int st = 64; st > 0; st >>= 1) {
        if (t < st) red[t] += red[t + st];
        __syncthreads();
    }
    if (t == 0) {
        float lam1 = expf(red[0]);
        float beta = 1.f / (1.f + expf(-lam1 * LAMBDA_INIT));
        g_beta = beta;
        *beta_slot = beta;
    }
}

// ---------------- K1: mask dtype sniffer ----------------
__global__ void detect_kernel(const unsigned char* __restrict__ raw) {
    __shared__ int cnt[4];
    if (threadIdx.x < 4) cnt[threadIdx.x] = 0;
    __syncthreads();
    for (int i = threadIdx.x; i < 16384; i += blockDim.x)
        if (raw[i]) atomicAdd(&cnt[i & 3], 1);
    __syncthreads();
    if (threadIdx.x == 0) {
        int kind;
        if (cnt[1] == 0 && cnt[2] == 0 && cnt[3] == 0) kind = 1;
        else if (cnt[0] == 0 && cnt[1] == 0)           kind = 2;
        else                                            kind = 0;
        g_mask_kind = kind;
    }
}

// ---------------- K2: mask transpose ----------------
__global__ void mask_transpose_kernel(const void* __restrict__ rawv) {
    __shared__ unsigned char tile[32][33];
    int b = blockIdx.z;
    int i0 = blockIdx.x * 32, j0 = blockIdx.y * 32;
    int tx = threadIdx.x, ty = threadIdx.y;
    int kind = g_mask_kind;
    size_t src = ((size_t)b * Nn + (j0 + ty)) * Nn + (i0 + tx);
    unsigned char v;
    if (kind == 0)      v = (((const unsigned char*)rawv)[src] != 0);
    else if (kind == 1) v = (((const int*)rawv)[src] != 0);
    else                v = (((const float*)rawv)[src] != 0.f);
    tile[ty][tx] = v;
    __syncthreads();
    g_maskT[((size_t)b * Nn + (i0 + ty)) * Nn + (j0 + tx)] = tile[tx][ty];
}

// ---------------- v projection -> bf16 hi/lo [n][e] ----------------
__global__ __launch_bounds__(256) void gemm_vproj_kernel(const float* __restrict__ X,
                                                         const float* __restrict__ W) {
    __shared__ float As[64][65];
    __shared__ float Bs[64][132];
    int t = threadIdx.x;
    int row0 = blockIdx.x * 64;
    int col0 = blockIdx.y * 128;
    int cg = t & 31;
    int rg = t >> 5;
    ull acc[8][2];
#pragma unroll
    for (int r = 0; r < 8; r++) { acc[r][0] = 0ULL; acc[r][1] = 0ULL; }

    for (int k0 = 0; k0 < Ee; k0 += 64) {
#pragma unroll
        for (int q = 0; q < 4; q++) {
            int idx = t + q * 256;
            int r = idx >> 4, e4 = (idx & 15) * 4;
            float4 v = *(const float4*)(X + (size_t)(row0 + r) * Ee + k0 + e4);
            As[r][e4 + 0] = v.x; As[r][e4 + 1] = v.y; As[r][e4 + 2] = v.z; As[r][e4 + 3] = v.w;
        }
#pragma unroll
        for (int q = 0; q < 8; q++) {
            int idx = t + q * 256;
            int f = idx >> 4, e4 = (idx & 15) * 4;
            float4 v = *(const float4*)(W + (size_t)(col0 + f) * Ee + k0 + e4);
            Bs[e4 + 0][f] = v.x; Bs[e4 + 1][f] = v.y; Bs[e4 + 2][f] = v.z; Bs[e4 + 3][f] = v.w;
        }
        __syncthreads();
#pragma unroll 4
        for (int k = 0; k < 64; k++) {
            float4 bv = *(const float4*)&Bs[k][cg * 4];
            ull blo = pack2(bv.x, bv.y);
            ull bhi = pack2(bv.z, bv.w);
#pragma unroll
            for (int r = 0; r < 8; r++) {
                float a = As[rg * 8 + r][k];
                ull a2 = pack2(a, a);
                acc[r][0] = ffma2(a2, blo, acc[r][0]);
                acc[r][1] = ffma2(a2, bhi, acc[r][1]);
            }
        }
        __syncthreads();
    }
#pragma unroll
    for (int r = 0; r < 8; r++) {
        float2 lo = unpack2(acc[r][0]);
        float2 hi = unpack2(acc[r][1]);
        uint32_t hp0 = cvt_bf16x2(lo.y, lo.x);
        uint32_t hp1 = cvt_bf16x2(hi.y, hi.x);
        float h0 = __uint_as_float(hp0 << 16);
        float h1 = __uint_as_float(hp0 & 0xFFFF0000u);
        float h2 = __uint_as_float(hp1 << 16);
        float h3 = __uint_as_float(hp1 & 0xFFFF0000u);
        uint32_t lp0 = cvt_bf16x2(lo.y - h1, lo.x - h0);
        uint32_t lp1 = cvt_bf16x2(hi.y - h3, hi.x - h2);
        size_t base = (size_t)(row0 + rg * 8 + r) * Ee + col0 + cg * 4;
        *(uint2*)(g_v_hi + base) = make_uint2(hp0, hp1);
        *(uint2*)(g_v_lo + base) = make_uint2(lp0, lp1);
    }
}

// ---------------- out projection gemm (fp32) ----------------
__global__ __launch_bounds__(256) void gemm_xw_kernel(const float* __restrict__ X,
                                                      const float* __restrict__ W,
                                                      float* __restrict__ Y) {
    __shared__ float As[64][65];
    __shared__ float Bs[64][132];
    int t = threadIdx.x;
    int row0 = blockIdx.x * 64;
    int col0 = blockIdx.y * 128;
    int cg = t & 31;
    int rg = t >> 5;
    ull acc[8][2];
#pragma unroll
    for (int r = 0; r < 8; r++) { acc[r][0] = 0ULL; acc[r][1] = 0ULL; }

    for (int k0 = 0; k0 < Ee; k0 += 64) {
#pragma unroll
        for (int q = 0; q < 4; q++) {
            int idx = t + q * 256;
            int r = idx >> 4, e4 = (idx & 15) * 4;
            float4 v = *(const float4*)(X + (size_t)(row0 + r) * Ee + k0 + e4);
            As[r][e4 + 0] = v.x; As[r][e4 + 1] = v.y; As[r][e4 + 2] = v.z; As[r][e4 + 3] = v.w;
        }
#pragma unroll
        for (int q = 0; q < 8; q++) {
            int idx = t + q * 256;
            int f = idx >> 4, e4 = (idx & 15) * 4;
            float4 v = *(const float4*)(W + (size_t)(col0 + f) * Ee + k0 + e4);
            Bs[e4 + 0][f] = v.x; Bs[e4 + 1][f] = v.y; Bs[e4 + 2][f] = v.z; Bs[e4 + 3][f] = v.w;
        }
        __syncthreads();
#pragma unroll 4
        for (int k = 0; k < 64; k++) {
            float4 bv = *(const float4*)&Bs[k][cg * 4];
            ull blo = pack2(bv.x, bv.y);
            ull bhi = pack2(bv.z, bv.w);
#pragma unroll
            for (int r = 0; r < 8; r++) {
                float a = As[rg * 8 + r][k];
                ull a2 = pack2(a, a);
                acc[r][0] = ffma2(a2, blo, acc[r][0]);
                acc[r][1] = ffma2(a2, bhi, acc[r][1]);
            }
        }
        __syncthreads();
    }
#pragma unroll
    for (int r = 0; r < 8; r++) {
        float2 lo = unpack2(acc[r][0]);
        float2 hi = unpack2(acc[r][1]);
        *(float4*)(Y + (size_t)(row0 + rg * 8 + r) * Ee + col0 + cg * 4) =
            make_float4(lo.x, lo.y, hi.x, hi.y);
    }
}

// ---------------- K4: softmax denominators ----------------
__global__ __launch_bounds__(256) void stats_kernel(const float* __restrict__ u,
                                                    const float* __restrict__ u_w,
                                                    const float* __restrict__ u_b) {
    int i = blockIdx.x, b = blockIdx.y, t = threadIdx.x;
    __shared__ ull s_w2[48];
    __shared__ ull s_b2[8];
    __shared__ float s_red[8][9];
    if (t < 48) { float w = u_w[t]; s_w2[t] = pack2(w, w); }
    if (t < 8)  { float bb = u_b[t]; s_b2[t] = pack2(bb, bb); }
    __syncthreads();

    int j0 = t * 4;
    unsigned mword = *(const unsigned*)(g_maskT + ((size_t)b * Nn + i) * Nn + j0);
    bool m0 = (mword & 0xFFu) != 0, m1 = ((mword >> 8) & 0xFFu) != 0;
    bool m2 = ((mword >> 16) & 0xFFu) != 0, m3 = ((mword >> 24) & 0xFFu) != 0;

    ulonglong2 u2[Uu];
#pragma unroll
    for (int c = 0; c < Uu; c++)
        u2[c] = *(const ulonglong2*)(u + ((size_t)(b * Uu + c) * Nn + i) * Nn + j0);

    float l[Oo];
#pragma unroll
    for (int o = 0; o < Oo; o++) {
        ull sa = s_b2[o], sb = s_b2[o];
#pragma unroll
        for (int c = 0; c < Uu; c++) {
            sa = ffma2(s_w2[o * Uu + c], u2[c].x, sa);
            sb = ffma2(s_w2[o * Uu + c], u2[c].y, sb);
        }
        float2 f0 = unpack2(sa), f1 = unpack2(sb);
        float acc = 0.f;
        if (!m0) acc += __expf(f0.x);
        if (!m1) acc += __expf(f0.y);
        if (!m2) acc += __expf(f1.x);
        if (!m3) acc += __expf(f1.y);
        l[o] = acc;
    }
#pragma unroll
    for (int o = 0; o < Oo; o++)
#pragma unroll
        for (int st = 16; st > 0; st >>= 1)
            l[o] += __shfl_xor_sync(0xFFFFFFFFu, l[o], st);
    int w = t >> 5, lane = t & 31;
    if (lane == 0) {
#pragma unroll
        for (int o = 0; o < Oo; o++) s_red[o][w] = l[o];
    }
    __syncthreads();
    if (t < 8) {
        float s = 0.f;
#pragma unroll
        for (int w2 = 0; w2 < 8; w2++) s += s_red[t][w2];
        g_l[((size_t)b * Oo + t) * Nn + i] = s;
    }
}

// ---------------- K5: fused attn compute + write + HMMA AV GEMM ----------------
// block = (b, 64-row i strip), 512 threads (16 warps), grid (16, 8)
// smem layout (bytes):
#define SB_W2    0                       // 48 ull = 384
#define SB_B2    384                     // 8 ull = 64
#define SB_BETA  448                     // 16
#define SB_RL    464                     // 512 floats = 2048 -> ends 2512
#define SB_A     2560                    // 4 heads x (64 rows x 272B) = 69632 -> ends 72192
#define SB_VHI   72192                   // 64 rows x 528B = 33792 -> ends 105984
#define SB_VLO   105984                  // 33792 -> ends 139776
#define SB_TOT   139776
#define A_HSTR   17408                   // per-head A stride
#define A_RSTR   272                     // A row stride (64 hi bf16 | 64 lo bf16, +16 pad)
#define V_RSTR   528                     // V row stride (256 bf16 = 512B, +16 pad)

__global__ __launch_bounds__(512, 1) void fused_kernel(const float* __restrict__ u,
                                                       const float* __restrict__ u_w,
                                                       const float* __restrict__ u_b,
                                                       float* __restrict__ attn_out) {
    extern __shared__ char smc[];
    const uint32_t smem_base = smem_u32(smc);
    ull*   s_w2   = (ull*)(smc + SB_W2);
    ull*   s_b2   = (ull*)(smc + SB_B2);
    float* s_beta = (float*)(smc + SB_BETA);
    float* s_rl   = (float*)(smc + SB_RL);

    const int t = threadIdx.x;
    const int wid = t >> 5;
    const int lane = t & 31;
    const int b = blockIdx.y;
    const int i0 = blockIdx.x * 64;

    if (t < 48)      { float w = u_w[t]; s_w2[t] = pack2(w, w); }
    else if (t < 56) { float bb = u_b[t - 48]; s_b2[t - 48] = pack2(bb, bb); }
    else if (t == 56) *s_beta = g_beta;
    if (t < 512) {
        int o = t >> 6, il = t & 63;
        s_rl[t] = 1.0f / g_l[((size_t)b * Oo + o) * Nn + i0 + il];
    }
    __syncthreads();

    const float beta = *s_beta;
    // phase A mapping: 2 rows x 4 j per thread
    const int jq = t & 15;
    const int iq = t >> 4;                 // 0..31
    // phase B mapping: warp -> (head, 16-row group)
    const int h_b = wid >> 2;
    const int ig = wid & 3;
    // ldmatrix lane addressing
    const int lg = lane >> 3, lr = lane & 7;
    const uint32_t a_lm_row = (uint32_t)(ig * 16 + (lg & 1) * 8 + lr);   // m
    const uint32_t a_lm_kh = (uint32_t)(lg >> 1);                        // k half (16B)
    const uint32_t b_lm_krow = (uint32_t)((lg & 1) * 8 + lr);            // k within 16
    const uint32_t b_lm_ncol = (uint32_t)(h_b * 64 + (lg >> 1) * 8);     // n base (d)

    float c[8][4];
#pragma unroll
    for (int nf = 0; nf < 8; nf++)
#pragma unroll
        for (int k = 0; k < 4; k++) c[nf][k] = 0.f;

    for (int jt = 0; jt < 16; jt++) {
        const int jg0 = jt * 64 + jq * 4;

        // ---- stage V hi/lo tile (gmem -> regs, hides latency under phase A) ----
        uint4 vstage[8];
#pragma unroll
        for (int q = 0; q < 8; q++) {
            int cidx = t + q * 512;                 // 4096 chunks of 16B
            int isLo = cidx >> 11;                  // 0 hi, 1 lo
            int r = (cidx >> 5) & 63;
            int k16 = cidx & 31;
            const __nv_bfloat16* src = (isLo ? g_v_lo : g_v_hi) +
                ((size_t)b * Nn + jt * 64 + r) * Ee + k16 * 8;
            vstage[q] = *(const uint4*)src;
        }

        // ---- phase A: scores -> attn -> gmem + bf16 hi/lo STS ----
#pragma unroll
        for (int r2 = 0; r2 < 2; r2++) {
            const int il = iq * 2 + r2;
            const int gi = i0 + il;
            unsigned mword = *(const unsigned*)(g_maskT + ((size_t)b * Nn + gi) * Nn + jg0);
            bool m0 = (mword & 0xFFu) != 0, m1 = ((mword >> 8) & 0xFFu) != 0;
            bool m2 = ((mword >> 16) & 0xFFu) != 0, m3 = ((mword >> 24) & 0xFFu) != 0;
            ulonglong2 u2[Uu];
#pragma unroll
            for (int cc = 0; cc < Uu; cc++)
                u2[cc] = *(const ulonglong2*)(u + ((size_t)(b * Uu + cc) * Nn + gi) * Nn + jg0);
            const uint32_t abyte = (uint32_t)(il * A_RSTR + jq * 8);
#pragma unroll
            for (int h = 0; h < Hh; h++) {
                int o0 = 2 * h, o1 = 2 * h + 1;
                ull sa0 = s_b2[o0], sb0 = s_b2[o0];
                ull sa1 = s_b2[o1], sb1 = s_b2[o1];
#pragma unroll
                for (int cc = 0; cc < Uu; cc++) {
                    sa0 = ffma2(s_w2[o0 * Uu + cc], u2[cc].x, sa0);
                    sb0 = ffma2(s_w2[o0 * Uu + cc], u2[cc].y, sb0);
                    sa1 = ffma2(s_w2[o1 * Uu + cc], u2[cc].x, sa1);
                    sb1 = ffma2(s_w2[o1 * Uu + cc], u2[cc].y, sb1);
                }
                float2 f00 = unpack2(sa0), f01 = unpack2(sb0);
                float2 f10 = unpack2(sa1), f11 = unpack2(sb1);
                float rl0 = s_rl[o0 * 64 + il];
                float rl1 = s_rl[o1 * 64 + il];
                float p00 = m0 ? 0.f : __expf(f00.x) * rl0;
                float p01 = m1 ? 0.f : __expf(f00.y) * rl0;
                float p02 = m2 ? 0.f : __expf(f01.x) * rl0;
                float p03 = m3 ? 0.f : __expf(f01.y) * rl0;
                float p10 = m0 ? 0.f : __expf(f10.x) * rl1;
                float p11 = m1 ? 0.f : __expf(f10.y) * rl1;
                float p12 = m2 ? 0.f : __expf(f11.x) * rl1;
                float p13 = m3 ? 0.f : __expf(f11.y) * rl1;
                float a0 = p00 - beta * p10;
                float a1 = p01 - beta * p11;
                float a2 = p02 - beta * p12;
                float a3 = p03 - beta * p13;
                *(float4*)(attn_out + ((size_t)(b * Hh + h) * Nn + gi) * Nn + jg0) =
                    make_float4(a0, a1, a2, a3);
                uint32_t hA = cvt_bf16x2(a1, a0);
                uint32_t hB = cvt_bf16x2(a3, a2);
                float h0 = __uint_as_float(hA << 16);
                float h1 = __uint_as_float(hA & 0xFFFF0000u);
                float h2 = __uint_as_float(hB << 16);
                float h3 = __uint_as_float(hB & 0xFFFF0000u);
                uint32_t lA = cvt_bf16x2(a1 - h1, a0 - h0);
                uint32_t lB = cvt_bf16x2(a3 - h3, a2 - h2);
                char* ap = smc + SB_A + h * A_HSTR + abyte;
                *(uint2*)(ap)       = make_uint2(hA, hB);      // hi at cols [0,128)
                *(uint2*)(ap + 128) = make_uint2(lA, lB);      // lo at cols [128,256)
            }
        }

        // ---- store staged V to smem ----
#pragma unroll
        for (int q = 0; q < 8; q++) {
            int cidx = t + q * 512;
            int isLo = cidx >> 11;
            int r = (cidx >> 5) & 63;
            int k16 = cidx & 31;
            char* dst = smc + (isLo ? SB_VLO : SB_VHI) + r * V_RSTR + k16 * 16;
            *(uint4*)dst = vstage[q];
        }
        __syncthreads();

        // ---- phase B: C += A(h_b, rows ig*16..+15) @ V ----
#pragma unroll
        for (int ks = 0; ks < 4; ks++) {
            // A fragments (hi, lo): 16x16 at k0 = ks*16
            uint32_t aAddrH = smem_base + SB_A + h_b * A_HSTR + a_lm_row * A_RSTR +
                              ks * 32 + a_lm_kh * 16;
            uint32_t ah0, ah1, ah2, ah3, al0, al1, al2, al3;
            ldmatrix_x4(ah0, ah1, ah2, ah3, aAddrH);
            ldmatrix_x4(al0, al1, al2, al3, aAddrH + 128);
#pragma unroll
            for (int np = 0; np < 4; np++) {
                uint32_t bAddr = smem_base + SB_VHI +
                                 (ks * 16 + b_lm_krow) * V_RSTR +
                                 (b_lm_ncol + np * 16) * 2;
                uint32_t bh0, bh1, bh2, bh3, bl0, bl1, bl2, bl3;
                ldmatrix_x4_trans(bh0, bh1, bh2, bh3, bAddr);
                ldmatrix_x4_trans(bl0, bl1, bl2, bl3, bAddr + (SB_VLO - SB_VHI));
                float* c0 = c[np * 2];
                float* c1 = c[np * 2 + 1];
                mma_bf16(c0, ah0, ah1, ah2, ah3, bh0, bh1);
                mma_bf16(c0, ah0, ah1, ah2, ah3, bl0, bl1);
                mma_bf16(c0, al0, al1, al2, al3, bh0, bh1);
                mma_bf16(c1, ah0, ah1, ah2, ah3, bh2, bh3);
                mma_bf16(c1, ah0, ah1, ah2, ah3, bl2, bl3);
                mma_bf16(c1, al0, al1, al2, al3, bh2, bh3);
            }
        }
        __syncthreads();
    }

    // ---- epilogue: C -> g_outpre ----
    {
        int r = lane >> 2, cq = lane & 3;
        int gi0 = i0 + ig * 16 + r;
        int gi1 = gi0 + 8;
        float* base0 = g_outpre + ((size_t)b * Nn + gi0) * Ee + h_b * 64 + cq * 2;
        float* base1 = g_outpre + ((size_t)b * Nn + gi1) * Ee + h_b * 64 + cq * 2;
#pragma unroll
        for (int nf = 0; nf < 8; nf++) {
            *(float2*)(base0 + nf * 8) = make_float2(c[nf][0], c[nf][1]);
            *(float2*)(base1 + nf * 8) = make_float2(c[nf][2], c[nf][3]);
        }
    }
}

// ---------------- launch ----------------
extern "C" void kernel_launch(void* const* d_in, const int* in_sizes, int n_in,
                              void* d_out, int out_size) {
    const float* x     = (const float*)d_in[0];
    const float* u     = (const float*)d_in[1];
    const void*  umask = d_in[2];
    const float* v_w   = (const float*)d_in[3];
    const float* out_w = (const float*)d_in[4];
    const float* u_w   = (const float*)d_in[5];
    const float* u_b   = (const float*)d_in[6];
    const float* lq    = (const float*)d_in[7];
    const float* lk    = (const float*)d_in[8];

    float* out = (float*)d_out;
    const size_t OUT_ELEMS  = (size_t)Bb * Nn * Ee;
    const size_t ATTN_ELEMS = (size_t)Bb * Hh * Nn * Nn;
    float* attn_out  = out + OUT_ELEMS;
    float* beta_slot = out + OUT_ELEMS + ATTN_ELEMS;

    float* optr = nullptr;
    cudaGetSymbolAddress((void**)&optr, g_outpre);

    static bool attr_set = false;
    if (!attr_set) {
        cudaFuncSetAttribute(fused_kernel, cudaFuncAttributeMaxDynamicSharedMemorySize, SB_TOT);
        attr_set = true;
    }

    beta_kernel<<<1, 128>>>(lq, lk, beta_slot);
    detect_kernel<<<1, 256>>>((const unsigned char*)umask);
    mask_transpose_kernel<<<dim3(32, 32, 8), dim3(32, 32)>>>(umask);
    gemm_vproj_kernel<<<dim3(128, 2), 256>>>(x, v_w);
    stats_kernel<<<dim3(Nn, Bb), 256>>>(u, u_w, u_b);
    fused_kernel<<<dim3(16, 8), 512, SB_TOT>>>(u, u_w, u_b, attn_out);
    gemm_xw_kernel<<<dim3(128, 2), 256>>>(optr, out_w, out);
    (void)in_sizes; (void)n_in; (void)out_size;
}

// round 6
// speedup vs baseline: 1.3163x; 1.0922x over previous
#include <cuda_runtime.h>
#include <cuda_bf16.h>
#include <math.h>
#include <stdint.h>

#define Bb 8
#define Nn 1024
#define Ee 256
#define Hh 4
#define Uu 6
#define Oo 8
#define LAMBDA_INIT 0.63212055882855767840f
#define LOG2E 1.44269504088896340736f

typedef unsigned long long ull;

// ---------------- scratch (static device memory; no allocation) ----------------
__device__ unsigned char g_maskT[(size_t)Bb * Nn * Nn];            // 8 MB
__device__ __nv_bfloat16 g_v_hi[(size_t)Bb * Nn * Ee];             // [row=b*N+n][e]
__device__ __nv_bfloat16 g_v_lo[(size_t)Bb * Nn * Ee];
__device__ __nv_bfloat16 g_x_hi[(size_t)Bb * Nn * Ee];
__device__ __nv_bfloat16 g_x_lo[(size_t)Bb * Nn * Ee];
__device__ __nv_bfloat16 g_op_hi[(size_t)Bb * Nn * Ee];            // out_pre bf16 hi/lo
__device__ __nv_bfloat16 g_op_lo[(size_t)Bb * Nn * Ee];
__device__ __nv_bfloat16 g_vw_hi[(size_t)Ee * Ee];
__device__ __nv_bfloat16 g_vw_lo[(size_t)Ee * Ee];
__device__ __nv_bfloat16 g_ow_hi[(size_t)Ee * Ee];
__device__ __nv_bfloat16 g_ow_lo[(size_t)Ee * Ee];
__device__ float g_l[(size_t)Bb * Oo * Nn];                        // softmax denominators
__device__ float g_beta;
__device__ int   g_mask_kind;                                      // 0=u8, 1=i32, 2=f32

// ---------------- helpers ----------------
__device__ __forceinline__ ull pack2(float a, float b) {
    ull r; asm("mov.b64 %0, {%1,%2};" : "=l"(r) : "f"(a), "f"(b)); return r;
}
__device__ __forceinline__ float2 unpack2(ull v) {
    float2 r; asm("mov.b64 {%0,%1}, %2;" : "=f"(r.x), "=f"(r.y) : "l"(v)); return r;
}
__device__ __forceinline__ ull ffma2(ull a, ull b, ull c) {
    ull d; asm("fma.rn.f32x2 %0, %1, %2, %3;" : "=l"(d) : "l"(a), "l"(b), "l"(c)); return d;
}
__device__ __forceinline__ uint32_t cvt_bf16x2(float a1, float a0) {
    uint32_t r; asm("cvt.rn.bf16x2.f32 %0, %1, %2;" : "=r"(r) : "f"(a1), "f"(a0)); return r;
}
__device__ __forceinline__ float ex2f(float x) {
    float r; asm("ex2.approx.f32 %0, %1;" : "=f"(r) : "f"(x)); return r;
}
__device__ __forceinline__ uint32_t smem_u32(const void* p) {
    uint32_t a;
    asm("{ .reg .u64 t; cvta.to.shared.u64 t, %1; cvt.u32.u64 %0, t; }" : "=r"(a) : "l"(p));
    return a;
}
__device__ __forceinline__ void ldmatrix_x4(uint32_t& r0, uint32_t& r1, uint32_t& r2,
                                            uint32_t& r3, uint32_t addr) {
    asm volatile("ldmatrix.sync.aligned.m8n8.x4.shared.b16 {%0,%1,%2,%3}, [%4];"
                 : "=r"(r0), "=r"(r1), "=r"(r2), "=r"(r3) : "r"(addr));
}
__device__ __forceinline__ void ldmatrix_x4_trans(uint32_t& r0, uint32_t& r1, uint32_t& r2,
                                                  uint32_t& r3, uint32_t addr) {
    asm volatile("ldmatrix.sync.aligned.m8n8.x4.trans.shared.b16 {%0,%1,%2,%3}, [%4];"
                 : "=r"(r0), "=r"(r1), "=r"(r2), "=r"(r3) : "r"(addr));
}
__device__ __forceinline__ void mma_bf16(float* c, uint32_t a0, uint32_t a1, uint32_t a2,
                                         uint32_t a3, uint32_t b0, uint32_t b1) {
    asm volatile(
        "mma.sync.aligned.m16n8k16.row.col.f32.bf16.bf16.f32 "
        "{%0,%1,%2,%3}, {%4,%5,%6,%7}, {%8,%9}, {%0,%1,%2,%3};"
        : "+f"(c[0]), "+f"(c[1]), "+f"(c[2]), "+f"(c[3])
        : "r"(a0), "r"(a1), "r"(a2), "r"(a3), "r"(b0), "r"(b1));
}

// ---------------- K0: beta ----------------
__global__ void beta_kernel(const float* __restrict__ lq, const float* __restrict__ lk,
                            float* __restrict__ beta_slot) {
    __shared__ float red[128];
    int t = threadIdx.x;
    red[t] = (t < 100) ? lq[t] * lk[t] : 0.f;
    __syncthreads();
    for (int st = 64; st > 0; st >>= 1) {
        if (t < st) red[t] += red[t + st];
        __syncthreads();
    }
    if (t == 0) {
        float lam1 = expf(red[0]);
        float beta = 1.f / (1.f + expf(-lam1 * LAMBDA_INIT));
        g_beta = beta;
        *beta_slot = beta;
    }
}

// ---------------- K1: mask dtype sniffer ----------------
__global__ void detect_kernel(const unsigned char* __restrict__ raw) {
    __shared__ int cnt[4];
    if (threadIdx.x < 4) cnt[threadIdx.x] = 0;
    __syncthreads();
    for (int i = threadIdx.x; i < 16384; i += blockDim.x)
        if (raw[i]) atomicAdd(&cnt[i & 3], 1);
    __syncthreads();
    if (threadIdx.x == 0) {
        int kind;
        if (cnt[1] == 0 && cnt[2] == 0 && cnt[3] == 0) kind = 1;
        else if (cnt[0] == 0 && cnt[1] == 0)           kind = 2;
        else                                            kind = 0;
        g_mask_kind = kind;
    }
}

// ---------------- K2: mask transpose ----------------
__global__ void mask_transpose_kernel(const void* __restrict__ rawv) {
    __shared__ unsigned char tile[32][33];
    int b = blockIdx.z;
    int i0 = blockIdx.x * 32, j0 = blockIdx.y * 32;
    int tx = threadIdx.x, ty = threadIdx.y;
    int kind = g_mask_kind;
    size_t src = ((size_t)b * Nn + (j0 + ty)) * Nn + (i0 + tx);
    unsigned char v;
    if (kind == 0)      v = (((const unsigned char*)rawv)[src] != 0);
    else if (kind == 1) v = (((const int*)rawv)[src] != 0);
    else                v = (((const float*)rawv)[src] != 0.f);
    tile[ty][tx] = v;
    __syncthreads();
    g_maskT[((size_t)b * Nn + (i0 + ty)) * Nn + (j0 + tx)] = tile[tx][ty];
}

// ---------------- split fp32 -> bf16 hi/lo ----------------
__global__ __launch_bounds__(256) void split_kernel(const float* __restrict__ in,
                                                    __nv_bfloat16* __restrict__ hi,
                                                    __nv_bfloat16* __restrict__ lo, int n4) {
    int idx = blockIdx.x * 256 + threadIdx.x;
    if (idx >= n4) return;
    float4 v = ((const float4*)in)[idx];
    uint32_t h0 = cvt_bf16x2(v.y, v.x);
    uint32_t h1 = cvt_bf16x2(v.w, v.z);
    float a0 = __uint_as_float(h0 << 16), a1 = __uint_as_float(h0 & 0xFFFF0000u);
    float a2 = __uint_as_float(h1 << 16), a3 = __uint_as_float(h1 & 0xFFFF0000u);
    uint32_t l0 = cvt_bf16x2(v.y - a1, v.x - a0);
    uint32_t l1 = cvt_bf16x2(v.w - a3, v.z - a2);
    ((uint2*)hi)[idx] = make_uint2(h0, h1);
    ((uint2*)lo)[idx] = make_uint2(l0, l1);
}

// ---------------- projection GEMM via HMMA: Y[row,f] = sum_e A[row,e]*W[f,e] ----------------
// tile 64x64, K chunks of 64, 256 threads (8 warps: 4 m x 2 n), 3 hi/lo combos.
#define GR_STR 144     // smem row stride bytes (64 bf16 = 128 + 16 pad)
template <int MODE>    // 0: fp32 Y; 1: bf16 hi/lo out (vproj)
__global__ __launch_bounds__(256) void gemm_mma_kernel(
    const __nv_bfloat16* __restrict__ Ahi, const __nv_bfloat16* __restrict__ Alo,
    const __nv_bfloat16* __restrict__ Whi, const __nv_bfloat16* __restrict__ Wlo,
    float* __restrict__ Y, __nv_bfloat16* __restrict__ Yhi, __nv_bfloat16* __restrict__ Ylo) {
    __shared__ char sm[4 * 64 * GR_STR];
    char* sAh = sm;
    char* sAl = sm + 64 * GR_STR;
    char* sWh = sm + 2 * 64 * GR_STR;
    char* sWl = sm + 3 * 64 * GR_STR;
    const uint32_t smb = smem_u32(sm);

    const int t = threadIdx.x;
    const int wid = t >> 5, lane = t & 31;
    const int row0 = blockIdx.x * 64;
    const int col0 = blockIdx.y * 64;
    const int mw = wid >> 1, nw = wid & 1;
    const int lr = lane & 7, quad = lane >> 3;
    const uint32_t aRow = (uint32_t)(mw * 16 + (quad & 1) * 8 + lr);
    const uint32_t aKoff = (uint32_t)((quad >> 1) * 16);
    const uint32_t bRow = (uint32_t)((quad >> 1) * 8 + lr);
    const uint32_t bKoff = (uint32_t)((quad & 1) * 16);

    float c[4][4];
#pragma unroll
    for (int nf = 0; nf < 4; nf++)
#pragma unroll
        for (int k = 0; k < 4; k++) c[nf][k] = 0.f;

    for (int kc = 0; kc < 4; kc++) {
        __syncthreads();
#pragma unroll
        for (int q = 0; q < 2; q++) {
            int idx = t + q * 256;
            int r = idx >> 3, c16 = idx & 7;
            *(uint4*)(sAh + r * GR_STR + c16 * 16) =
                ((const uint4*)(Ahi + (size_t)(row0 + r) * Ee + kc * 64))[c16];
            *(uint4*)(sAl + r * GR_STR + c16 * 16) =
                ((const uint4*)(Alo + (size_t)(row0 + r) * Ee + kc * 64))[c16];
            *(uint4*)(sWh + r * GR_STR + c16 * 16) =
                ((const uint4*)(Whi + (size_t)(col0 + r) * Ee + kc * 64))[c16];
            *(uint4*)(sWl + r * GR_STR + c16 * 16) =
                ((const uint4*)(Wlo + (size_t)(col0 + r) * Ee + kc * 64))[c16];
        }
        __syncthreads();
#pragma unroll
        for (int ks = 0; ks < 4; ks++) {
            uint32_t aBase = smb + aRow * GR_STR + ks * 32 + aKoff;
            uint32_t ah0, ah1, ah2, ah3, al0, al1, al2, al3;
            ldmatrix_x4(ah0, ah1, ah2, ah3, aBase);
            ldmatrix_x4(al0, al1, al2, al3, aBase + 64 * GR_STR);
#pragma unroll
            for (int np = 0; np < 2; np++) {
                uint32_t bBase = smb + 2 * 64 * GR_STR +
                                 (nw * 32 + np * 16 + bRow) * GR_STR + ks * 32 + bKoff;
                uint32_t bh0, bh1, bh2, bh3, bl0, bl1, bl2, bl3;
                ldmatrix_x4(bh0, bh1, bh2, bh3, bBase);
                ldmatrix_x4(bl0, bl1, bl2, bl3, bBase + 64 * GR_STR);
                float* c0 = c[np * 2];
                float* c1 = c[np * 2 + 1];
                mma_bf16(c0, ah0, ah1, ah2, ah3, bh0, bh1);
                mma_bf16(c0, ah0, ah1, ah2, ah3, bl0, bl1);
                mma_bf16(c0, al0, al1, al2, al3, bh0, bh1);
                mma_bf16(c1, ah0, ah1, ah2, ah3, bh2, bh3);
                mma_bf16(c1, ah0, ah1, ah2, ah3, bl2, bl3);
                mma_bf16(c1, al0, al1, al2, al3, bh2, bh3);
            }
        }
    }

    int r0 = row0 + mw * 16 + (lane >> 2);
    int colb = col0 + nw * 32 + (lane & 3) * 2;
#pragma unroll
    for (int nf = 0; nf < 4; nf++) {
        int col = colb + nf * 8;
        if (MODE == 0) {
            *(float2*)(Y + (size_t)r0 * Ee + col) = make_float2(c[nf][0], c[nf][1]);
            *(float2*)(Y + (size_t)(r0 + 8) * Ee + col) = make_float2(c[nf][2], c[nf][3]);
        } else {
            uint32_t h0 = cvt_bf16x2(c[nf][1], c[nf][0]);
            float e0 = __uint_as_float(h0 << 16), e1 = __uint_as_float(h0 & 0xFFFF0000u);
            uint32_t l0 = cvt_bf16x2(c[nf][1] - e1, c[nf][0] - e0);
            uint32_t h1 = cvt_bf16x2(c[nf][3], c[nf][2]);
            float e2 = __uint_as_float(h1 << 16), e3 = __uint_as_float(h1 & 0xFFFF0000u);
            uint32_t l1 = cvt_bf16x2(c[nf][3] - e3, c[nf][2] - e2);
            ((uint32_t*)Yhi)[((size_t)r0 * Ee + col) >> 1] = h0;
            ((uint32_t*)Ylo)[((size_t)r0 * Ee + col) >> 1] = l0;
            ((uint32_t*)Yhi)[((size_t)(r0 + 8) * Ee + col) >> 1] = h1;
            ((uint32_t*)Ylo)[((size_t)(r0 + 8) * Ee + col) >> 1] = l1;
        }
    }
}

// ---------------- K4: softmax denominators (exp2-folded weights) ----------------
__global__ __launch_bounds__(256) void stats_kernel(const float* __restrict__ u,
                                                    const float* __restrict__ u_w,
                                                    const float* __restrict__ u_b) {
    int i = blockIdx.x, b = blockIdx.y, t = threadIdx.x;
    __shared__ ull s_w2[48];
    __shared__ ull s_b2[8];
    __shared__ float s_red[8][9];
    if (t < 48) { float w = u_w[t] * LOG2E; s_w2[t] = pack2(w, w); }
    if (t < 8)  { float bb = u_b[t] * LOG2E; s_b2[t] = pack2(bb, bb); }
    __syncthreads();

    int j0 = t * 4;
    unsigned mword = *(const unsigned*)(g_maskT + ((size_t)b * Nn + i) * Nn + j0);
    bool m0 = (mword & 0xFFu) != 0, m1 = ((mword >> 8) & 0xFFu) != 0;
    bool m2 = ((mword >> 16) & 0xFFu) != 0, m3 = ((mword >> 24) & 0xFFu) != 0;

    ulonglong2 u2[Uu];
#pragma unroll
    for (int c = 0; c < Uu; c++)
        u2[c] = *(const ulonglong2*)(u + ((size_t)(b * Uu + c) * Nn + i) * Nn + j0);

    float l[Oo];
#pragma unroll
    for (int o = 0; o < Oo; o++) {
        ull sa = s_b2[o], sb = s_b2[o];
#pragma unroll
        for (int c = 0; c < Uu; c++) {
            sa = ffma2(s_w2[o * Uu + c], u2[c].x, sa);
            sb = ffma2(s_w2[o * Uu + c], u2[c].y, sb);
        }
        float2 f0 = unpack2(sa), f1 = unpack2(sb);
        float acc = 0.f;
        if (!m0) acc += ex2f(f0.x);
        if (!m1) acc += ex2f(f0.y);
        if (!m2) acc += ex2f(f1.x);
        if (!m3) acc += ex2f(f1.y);
        l[o] = acc;
    }
#pragma unroll
    for (int o = 0; o < Oo; o++)
#pragma unroll
        for (int st = 16; st > 0; st >>= 1)
            l[o] += __shfl_xor_sync(0xFFFFFFFFu, l[o], st);
    int w = t >> 5, lane = t & 31;
    if (lane == 0) {
#pragma unroll
        for (int o = 0; o < Oo; o++) s_red[o][w] = l[o];
    }
    __syncthreads();
    if (t < 8) {
        float s = 0.f;
#pragma unroll
        for (int w2 = 0; w2 < 8; w2++) s += s_red[t][w2];
        g_l[((size_t)b * Oo + t) * Nn + i] = s;
    }
}

// ---------------- K5: fused attn compute + write + HMMA AV GEMM ----------------
#define SB_W2    0
#define SB_B2    384
#define SB_BETA  448
#define SB_RL    464
#define SB_A     2560
#define SB_VHI   72192
#define SB_VLO   105984
#define SB_TOT   139776
#define A_HSTR   17408
#define A_RSTR   272
#define V_RSTR   528

__global__ __launch_bounds__(512, 1) void fused_kernel(const float* __restrict__ u,
                                                       const float* __restrict__ u_w,
                                                       const float* __restrict__ u_b,
                                                       float* __restrict__ attn_out) {
    extern __shared__ char smc[];
    const uint32_t smem_base = smem_u32(smc);
    ull*   s_w2   = (ull*)(smc + SB_W2);
    ull*   s_b2   = (ull*)(smc + SB_B2);
    float* s_beta = (float*)(smc + SB_BETA);
    float* s_rl   = (float*)(smc + SB_RL);

    const int t = threadIdx.x;
    const int wid = t >> 5;
    const int lane = t & 31;
    const int b = blockIdx.y;
    const int i0 = blockIdx.x * 64;

    if (t < 48)      { float w = u_w[t] * LOG2E; s_w2[t] = pack2(w, w); }
    else if (t < 56) { float bb = u_b[t - 48] * LOG2E; s_b2[t - 48] = pack2(bb, bb); }
    else if (t == 56) *s_beta = g_beta;
    {
        int o = t >> 6, il = t & 63;
        s_rl[t] = 1.0f / g_l[((size_t)b * Oo + o) * Nn + i0 + il];
    }
    __syncthreads();

    const float beta = *s_beta;
    const int jq = t & 15;
    const int iq = t >> 4;
    const int h_b = wid >> 2;
    const int ig = wid & 3;
    const int lg = lane >> 3, lr = lane & 7;
    const uint32_t a_lm_row = (uint32_t)(ig * 16 + (lg & 1) * 8 + lr);
    const uint32_t a_lm_kh = (uint32_t)(lg >> 1);
    const uint32_t b_lm_krow = (uint32_t)((lg & 1) * 8 + lr);
    const uint32_t b_lm_ncol = (uint32_t)(h_b * 64 + (lg >> 1) * 8);

    float c[8][4];
#pragma unroll
    for (int nf = 0; nf < 8; nf++)
#pragma unroll
        for (int k = 0; k < 4; k++) c[nf][k] = 0.f;

    for (int jt = 0; jt < 16; jt++) {
        const int jg0 = jt * 64 + jq * 4;
        const int il0 = iq * 2, il1 = iq * 2 + 1;
        const int gi0 = i0 + il0, gi1 = i0 + il1;

        // ---- issue u + mask LDGs for both rows up front (max MLP) ----
        ulonglong2 uA[Uu], uB[Uu];
        unsigned mwA = *(const unsigned*)(g_maskT + ((size_t)b * Nn + gi0) * Nn + jg0);
        unsigned mwB = *(const unsigned*)(g_maskT + ((size_t)b * Nn + gi1) * Nn + jg0);
#pragma unroll
        for (int cc = 0; cc < Uu; cc++) {
            uA[cc] = *(const ulonglong2*)(u + ((size_t)(b * Uu + cc) * Nn + gi0) * Nn + jg0);
            uB[cc] = *(const ulonglong2*)(u + ((size_t)(b * Uu + cc) * Nn + gi1) * Nn + jg0);
        }

        // ---- V tile: load + STS immediately (prev phase B done at loop top) ----
#pragma unroll
        for (int q = 0; q < 8; q++) {
            int cidx = t + q * 512;
            int isLo = cidx >> 11;
            int r = (cidx >> 5) & 63;
            int k16 = cidx & 31;
            const __nv_bfloat16* src = (isLo ? g_v_lo : g_v_hi) +
                ((size_t)b * Nn + jt * 64 + r) * Ee + k16 * 8;
            uint4 vv = *(const uint4*)src;
            char* dst = smc + (isLo ? SB_VLO : SB_VHI) + r * V_RSTR + k16 * 16;
            *(uint4*)dst = vv;
        }

        // ---- phase A ----
#pragma unroll
        for (int r2 = 0; r2 < 2; r2++) {
            const int il = r2 ? il1 : il0;
            const int gi = r2 ? gi1 : gi0;
            const unsigned mword = r2 ? mwB : mwA;
            const ulonglong2* u2 = r2 ? uB : uA;
            bool m0 = (mword & 0xFFu) != 0, m1 = ((mword >> 8) & 0xFFu) != 0;
            bool m2 = ((mword >> 16) & 0xFFu) != 0, m3 = ((mword >> 24) & 0xFFu) != 0;
            const uint32_t abyte = (uint32_t)(il * A_RSTR + jq * 8);
#pragma unroll
            for (int h = 0; h < Hh; h++) {
                int o0 = 2 * h, o1 = 2 * h + 1;
                ull sa0 = s_b2[o0], sb0 = s_b2[o0];
                ull sa1 = s_b2[o1], sb1 = s_b2[o1];
#pragma unroll
                for (int cc = 0; cc < Uu; cc++) {
                    sa0 = ffma2(s_w2[o0 * Uu + cc], u2[cc].x, sa0);
                    sb0 = ffma2(s_w2[o0 * Uu + cc], u2[cc].y, sb0);
                    sa1 = ffma2(s_w2[o1 * Uu + cc], u2[cc].x, sa1);
                    sb1 = ffma2(s_w2[o1 * Uu + cc], u2[cc].y, sb1);
                }
                float2 f00 = unpack2(sa0), f01 = unpack2(sb0);
                float2 f10 = unpack2(sa1), f11 = unpack2(sb1);
                float rl0 = s_rl[o0 * 64 + il];
                float rl1 = s_rl[o1 * 64 + il];
                float p00 = m0 ? 0.f : ex2f(f00.x) * rl0;
                float p01 = m1 ? 0.f : ex2f(f00.y) * rl0;
                float p02 = m2 ? 0.f : ex2f(f01.x) * rl0;
                float p03 = m3 ? 0.f : ex2f(f01.y) * rl0;
                float p10 = m0 ? 0.f : ex2f(f10.x) * rl1;
                float p11 = m1 ? 0.f : ex2f(f10.y) * rl1;
                float p12 = m2 ? 0.f : ex2f(f11.x) * rl1;
                float p13 = m3 ? 0.f : ex2f(f11.y) * rl1;
                float a0 = p00 - beta * p10;
                float a1 = p01 - beta * p11;
                float a2 = p02 - beta * p12;
                float a3 = p03 - beta * p13;
                *(float4*)(attn_out + ((size_t)(b * Hh + h) * Nn + gi) * Nn + jg0) =
                    make_float4(a0, a1, a2, a3);
                uint32_t hA = cvt_bf16x2(a1, a0);
                uint32_t hB = cvt_bf16x2(a3, a2);
                float h0 = __uint_as_float(hA << 16);
                float h1 = __uint_as_float(hA & 0xFFFF0000u);
                float h2 = __uint_as_float(hB << 16);
                float h3 = __uint_as_float(hB & 0xFFFF0000u);
                uint32_t lA = cvt_bf16x2(a1 - h1, a0 - h0);
                uint32_t lB = cvt_bf16x2(a3 - h3, a2 - h2);
                char* ap = smc + SB_A + h * A_HSTR + abyte;
                *(uint2*)(ap)       = make_uint2(hA, hB);
                *(uint2*)(ap + 128) = make_uint2(lA, lB);
            }
        }
        __syncthreads();

        // ---- phase B ----
#pragma unroll
        for (int ks = 0; ks < 4; ks++) {
            uint32_t aAddrH = smem_base + SB_A + h_b * A_HSTR + a_lm_row * A_RSTR +
                              ks * 32 + a_lm_kh * 16;
            uint32_t ah0, ah1, ah2, ah3, al0, al1, al2, al3;
            ldmatrix_x4(ah0, ah1, ah2, ah3, aAddrH);
            ldmatrix_x4(al0, al1, al2, al3, aAddrH + 128);
#pragma unroll
            for (int np = 0; np < 4; np++) {
                uint32_t bAddr = smem_base + SB_VHI +
                                 (ks * 16 + b_lm_krow) * V_RSTR +
                                 (b_lm_ncol + np * 16) * 2;
                uint32_t bh0, bh1, bh2, bh3, bl0, bl1, bl2, bl3;
                ldmatrix_x4_trans(bh0, bh1, bh2, bh3, bAddr);
                ldmatrix_x4_trans(bl0, bl1, bl2, bl3, bAddr + (SB_VLO - SB_VHI));
                float* c0 = c[np * 2];
                float* c1 = c[np * 2 + 1];
                mma_bf16(c0, ah0, ah1, ah2, ah3, bh0, bh1);
                mma_bf16(c0, ah0, ah1, ah2, ah3, bl0, bl1);
                mma_bf16(c0, al0, al1, al2, al3, bh0, bh1);
                mma_bf16(c1, ah0, ah1, ah2, ah3, bh2, bh3);
                mma_bf16(c1, ah0, ah1, ah2, ah3, bl2, bl3);
                mma_bf16(c1, al0, al1, al2, al3, bh2, bh3);
            }
        }
        __syncthreads();
    }

    // ---- epilogue: C -> g_op_hi/lo (bf16 split) ----
    {
        int r = lane >> 2, cq = lane & 3;
        int gi0 = i0 + ig * 16 + r;
        int gi1 = gi0 + 8;
#pragma unroll
        for (int nf = 0; nf < 8; nf++) {
            int col = h_b * 64 + nf * 8 + cq * 2;
            uint32_t h0 = cvt_bf16x2(c[nf][1], c[nf][0]);
            float e0 = __uint_as_float(h0 << 16), e1 = __uint_as_float(h0 & 0xFFFF0000u);
            uint32_t l0 = cvt_bf16x2(c[nf][1] - e1, c[nf][0] - e0);
            uint32_t h1 = cvt_bf16x2(c[nf][3], c[nf][2]);
            float e2 = __uint_as_float(h1 << 16), e3 = __uint_as_float(h1 & 0xFFFF0000u);
            uint32_t l1 = cvt_bf16x2(c[nf][3] - e3, c[nf][2] - e2);
            ((uint32_t*)g_op_hi)[(((size_t)b * Nn + gi0) * Ee + col) >> 1] = h0;
            ((uint32_t*)g_op_lo)[(((size_t)b * Nn + gi0) * Ee + col) >> 1] = l0;
            ((uint32_t*)g_op_hi)[(((size_t)b * Nn + gi1) * Ee + col) >> 1] = h1;
            ((uint32_t*)g_op_lo)[(((size_t)b * Nn + gi1) * Ee + col) >> 1] = l1;
        }
    }
}

// ---------------- launch ----------------
extern "C" void kernel_launch(void* const* d_in, const int* in_sizes, int n_in,
                              void* d_out, int out_size) {
    const float* x     = (const float*)d_in[0];
    const float* u     = (const float*)d_in[1];
    const void*  umask = d_in[2];
    const float* v_w   = (const float*)d_in[3];
    const float* out_w = (const float*)d_in[4];
    const float* u_w   = (const float*)d_in[5];
    const float* u_b   = (const float*)d_in[6];
    const float* lq    = (const float*)d_in[7];
    const float* lk    = (const float*)d_in[8];

    float* out = (float*)d_out;
    const size_t OUT_ELEMS  = (size_t)Bb * Nn * Ee;
    const size_t ATTN_ELEMS = (size_t)Bb * Hh * Nn * Nn;
    float* attn_out  = out + OUT_ELEMS;
    float* beta_slot = out + OUT_ELEMS + ATTN_ELEMS;

    __nv_bfloat16 *xhi, *xlo, *vwhi, *vwlo, *owhi, *owlo, *vhi, *vlo, *ophi, *oplo;
    cudaGetSymbolAddress((void**)&xhi, g_x_hi);
    cudaGetSymbolAddress((void**)&xlo, g_x_lo);
    cudaGetSymbolAddress((void**)&vwhi, g_vw_hi);
    cudaGetSymbolAddress((void**)&vwlo, g_vw_lo);
    cudaGetSymbolAddress((void**)&owhi, g_ow_hi);
    cudaGetSymbolAddress((void**)&owlo, g_ow_lo);
    cudaGetSymbolAddress((void**)&vhi, g_v_hi);
    cudaGetSymbolAddress((void**)&vlo, g_v_lo);
    cudaGetSymbolAddress((void**)&ophi, g_op_hi);
    cudaGetSymbolAddress((void**)&oplo, g_op_lo);

    static bool attr_set = false;
    if (!attr_set) {
        cudaFuncSetAttribute(fused_kernel, cudaFuncAttributeMaxDynamicSharedMemorySize, SB_TOT);
        attr_set = true;
    }

    beta_kernel<<<1, 128>>>(lq, lk, beta_slot);
    detect_kernel<<<1, 256>>>((const unsigned char*)umask);
    mask_transpose_kernel<<<dim3(32, 32, 8), dim3(32, 32)>>>(umask);
    split_kernel<<<2048, 256>>>(x, xhi, xlo, (int)(OUT_ELEMS / 4));
    split_kernel<<<64, 256>>>(v_w, vwhi, vwlo, Ee * Ee / 4);
    split_kernel<<<64, 256>>>(out_w, owhi, owlo, Ee * Ee / 4);
    gemm_mma_kernel<1><<<dim3(128, 4), 256>>>(xhi, xlo, vwhi, vwlo, nullptr, vhi, vlo);
    stats_kernel<<<dim3(Nn, Bb), 256>>>(u, u_w, u_b);
    fused_kernel<<<dim3(16, 8), 512, SB_TOT>>>(u, u_w, u_b, attn_out);
    gemm_mma_kernel<0><<<dim3(128, 4), 256>>>(ophi, oplo, owhi, owlo, out, nullptr, nullptr);
    (void)in_sizes; (void)n_in; (void)out_size;
}

// round 7
// speedup vs baseline: 1.7802x; 1.3524x over previous
#include <cuda_runtime.h>
#include <cuda_bf16.h>
#include <math.h>
#include <stdint.h>

#define Bb 8
#define Nn 1024
#define Ee 256
#define Hh 4
#define Uu 6
#define Oo 8
#define LAMBDA_INIT 0.63212055882855767840f
#define LOG2E 1.44269504088896340736f

typedef unsigned long long ull;

// ---------------- scratch (static device memory; no allocation) ----------------
__device__ unsigned char g_maskT[(size_t)Bb * Nn * Nn];
__device__ __nv_bfloat16 g_v_hi[(size_t)Bb * Nn * Ee];
__device__ __nv_bfloat16 g_v_lo[(size_t)Bb * Nn * Ee];
__device__ __nv_bfloat16 g_x_hi[(size_t)Bb * Nn * Ee];
__device__ __nv_bfloat16 g_x_lo[(size_t)Bb * Nn * Ee];
__device__ __nv_bfloat16 g_op_hi[(size_t)Bb * Nn * Ee];
__device__ __nv_bfloat16 g_op_lo[(size_t)Bb * Nn * Ee];
__device__ __nv_bfloat16 g_vw_hi[(size_t)Ee * Ee];
__device__ __nv_bfloat16 g_vw_lo[(size_t)Ee * Ee];
__device__ __nv_bfloat16 g_ow_hi[(size_t)Ee * Ee];
__device__ __nv_bfloat16 g_ow_lo[(size_t)Ee * Ee];
__device__ float g_l[(size_t)Bb * Oo * Nn];
__device__ float g_beta;
__device__ int   g_mask_kind;

// ---------------- helpers ----------------
__device__ __forceinline__ ull pack2(float a, float b) {
    ull r; asm("mov.b64 %0, {%1,%2};" : "=l"(r) : "f"(a), "f"(b)); return r;
}
__device__ __forceinline__ float2 unpack2(ull v) {
    float2 r; asm("mov.b64 {%0,%1}, %2;" : "=f"(r.x), "=f"(r.y) : "l"(v)); return r;
}
__device__ __forceinline__ ull ffma2(ull a, ull b, ull c) {
    ull d; asm("fma.rn.f32x2 %0, %1, %2, %3;" : "=l"(d) : "l"(a), "l"(b), "l"(c)); return d;
}
__device__ __forceinline__ uint32_t cvt_bf16x2(float a1, float a0) {
    uint32_t r; asm("cvt.rn.bf16x2.f32 %0, %1, %2;" : "=r"(r) : "f"(a1), "f"(a0)); return r;
}
__device__ __forceinline__ float ex2f(float x) {
    float r; asm("ex2.approx.f32 %0, %1;" : "=f"(r) : "f"(x)); return r;
}
__device__ __forceinline__ uint32_t smem_u32(const void* p) {
    uint32_t a;
    asm("{ .reg .u64 t; cvta.to.shared.u64 t, %1; cvt.u32.u64 %0, t; }" : "=r"(a) : "l"(p));
    return a;
}
__device__ __forceinline__ void ldmatrix_x4(uint32_t& r0, uint32_t& r1, uint32_t& r2,
                                            uint32_t& r3, uint32_t addr) {
    asm volatile("ldmatrix.sync.aligned.m8n8.x4.shared.b16 {%0,%1,%2,%3}, [%4];"
                 : "=r"(r0), "=r"(r1), "=r"(r2), "=r"(r3) : "r"(addr));
}
__device__ __forceinline__ void ldmatrix_x4_trans(uint32_t& r0, uint32_t& r1, uint32_t& r2,
                                                  uint32_t& r3, uint32_t addr) {
    asm volatile("ldmatrix.sync.aligned.m8n8.x4.trans.shared.b16 {%0,%1,%2,%3}, [%4];"
                 : "=r"(r0), "=r"(r1), "=r"(r2), "=r"(r3) : "r"(addr));
}
__device__ __forceinline__ void mma_bf16(float* c, uint32_t a0, uint32_t a1, uint32_t a2,
                                         uint32_t a3, uint32_t b0, uint32_t b1) {
    asm volatile(
        "mma.sync.aligned.m16n8k16.row.col.f32.bf16.bf16.f32 "
        "{%0,%1,%2,%3}, {%4,%5,%6,%7}, {%8,%9}, {%0,%1,%2,%3};"
        : "+f"(c[0]), "+f"(c[1]), "+f"(c[2]), "+f"(c[3])
        : "r"(a0), "r"(a1), "r"(a2), "r"(a3), "r"(b0), "r"(b1));
}

// ---------------- K1: detect mask dtype + beta (merged) ----------------
__global__ void detect_beta_kernel(const unsigned char* __restrict__ raw,
                                   const float* __restrict__ lq,
                                   const float* __restrict__ lk,
                                   float* __restrict__ beta_slot) {
    __shared__ int cnt[4];
    __shared__ float red[128];
    int t = threadIdx.x;
    if (t < 4) cnt[t] = 0;
    if (t < 128) red[t] = (t < 100) ? lq[t] * lk[t] : 0.f;
    __syncthreads();
    for (int i = t; i < 16384; i += blockDim.x)
        if (raw[i]) atomicAdd(&cnt[i & 3], 1);
    for (int st = 64; st > 0; st >>= 1) {
        if (t < st) red[t] += red[t + st];
        __syncthreads();
    }
    if (t == 0) {
        int kind;
        if (cnt[1] == 0 && cnt[2] == 0 && cnt[3] == 0) kind = 1;
        else if (cnt[0] == 0 && cnt[1] == 0)           kind = 2;
        else                                            kind = 0;
        g_mask_kind = kind;
        float lam1 = expf(red[0]);
        float beta = 1.f / (1.f + expf(-lam1 * LAMBDA_INIT));
        g_beta = beta;
        *beta_slot = beta;
    }
}

// ---------------- K2: mask transpose ----------------
__global__ void mask_transpose_kernel(const void* __restrict__ rawv) {
    __shared__ unsigned char tile[32][33];
    int b = blockIdx.z;
    int i0 = blockIdx.x * 32, j0 = blockIdx.y * 32;
    int tx = threadIdx.x, ty = threadIdx.y;
    int kind = g_mask_kind;
    size_t src = ((size_t)b * Nn + (j0 + ty)) * Nn + (i0 + tx);
    unsigned char v;
    if (kind == 0)      v = (((const unsigned char*)rawv)[src] != 0);
    else if (kind == 1) v = (((const int*)rawv)[src] != 0);
    else                v = (((const float*)rawv)[src] != 0.f);
    tile[ty][tx] = v;
    __syncthreads();
    g_maskT[((size_t)b * Nn + (i0 + ty)) * Nn + (j0 + tx)] = tile[tx][ty];
}

// ---------------- K3: split x, v_w, out_w -> bf16 hi/lo (one kernel) ----------------
#define NX4 ((int)((size_t)Bb * Nn * Ee / 4))
#define NW4 (Ee * Ee / 4)
__global__ __launch_bounds__(256) void split_all_kernel(const float* __restrict__ x,
                                                        const float* __restrict__ vw,
                                                        const float* __restrict__ ow) {
    int idx = blockIdx.x * 256 + threadIdx.x;
    const float* src;
    uint2 *hid, *lod;
    int li;
    if (idx < NX4) {
        src = x; hid = (uint2*)g_x_hi; lod = (uint2*)g_x_lo; li = idx;
    } else if (idx < NX4 + NW4) {
        src = vw; hid = (uint2*)g_vw_hi; lod = (uint2*)g_vw_lo; li = idx - NX4;
    } else if (idx < NX4 + 2 * NW4) {
        src = ow; hid = (uint2*)g_ow_hi; lod = (uint2*)g_ow_lo; li = idx - NX4 - NW4;
    } else return;
    float4 v = ((const float4*)src)[li];
    uint32_t h0 = cvt_bf16x2(v.y, v.x);
    uint32_t h1 = cvt_bf16x2(v.w, v.z);
    float a0 = __uint_as_float(h0 << 16), a1 = __uint_as_float(h0 & 0xFFFF0000u);
    float a2 = __uint_as_float(h1 << 16), a3 = __uint_as_float(h1 & 0xFFFF0000u);
    uint32_t l0 = cvt_bf16x2(v.y - a1, v.x - a0);
    uint32_t l1 = cvt_bf16x2(v.w - a3, v.z - a2);
    hid[li] = make_uint2(h0, h1);
    lod[li] = make_uint2(l0, l1);
}

// ---------------- projection GEMM via HMMA ----------------
#define GR_STR 144
template <int MODE>
__global__ __launch_bounds__(256) void gemm_mma_kernel(
    const __nv_bfloat16* __restrict__ Ahi, const __nv_bfloat16* __restrict__ Alo,
    const __nv_bfloat16* __restrict__ Whi, const __nv_bfloat16* __restrict__ Wlo,
    float* __restrict__ Y, __nv_bfloat16* __restrict__ Yhi, __nv_bfloat16* __restrict__ Ylo) {
    __shared__ char sm[4 * 64 * GR_STR];
    char* sAh = sm;
    char* sAl = sm + 64 * GR_STR;
    char* sWh = sm + 2 * 64 * GR_STR;
    char* sWl = sm + 3 * 64 * GR_STR;
    const uint32_t smb = smem_u32(sm);

    const int t = threadIdx.x;
    const int wid = t >> 5, lane = t & 31;
    const int row0 = blockIdx.x * 64;
    const int col0 = blockIdx.y * 64;
    const int mw = wid >> 1, nw = wid & 1;
    const int lr = lane & 7, quad = lane >> 3;
    const uint32_t aRow = (uint32_t)(mw * 16 + (quad & 1) * 8 + lr);
    const uint32_t aKoff = (uint32_t)((quad >> 1) * 16);
    const uint32_t bRow = (uint32_t)((quad >> 1) * 8 + lr);
    const uint32_t bKoff = (uint32_t)((quad & 1) * 16);

    float c[4][4];
#pragma unroll
    for (int nf = 0; nf < 4; nf++)
#pragma unroll
        for (int k = 0; k < 4; k++) c[nf][k] = 0.f;

    for (int kc = 0; kc < 4; kc++) {
        __syncthreads();
#pragma unroll
        for (int q = 0; q < 2; q++) {
            int idx = t + q * 256;
            int r = idx >> 3, c16 = idx & 7;
            *(uint4*)(sAh + r * GR_STR + c16 * 16) =
                ((const uint4*)(Ahi + (size_t)(row0 + r) * Ee + kc * 64))[c16];
            *(uint4*)(sAl + r * GR_STR + c16 * 16) =
                ((const uint4*)(Alo + (size_t)(row0 + r) * Ee + kc * 64))[c16];
            *(uint4*)(sWh + r * GR_STR + c16 * 16) =
                ((const uint4*)(Whi + (size_t)(col0 + r) * Ee + kc * 64))[c16];
            *(uint4*)(sWl + r * GR_STR + c16 * 16) =
                ((const uint4*)(Wlo + (size_t)(col0 + r) * Ee + kc * 64))[c16];
        }
        __syncthreads();
#pragma unroll
        for (int ks = 0; ks < 4; ks++) {
            uint32_t aBase = smb + aRow * GR_STR + ks * 32 + aKoff;
            uint32_t ah0, ah1, ah2, ah3, al0, al1, al2, al3;
            ldmatrix_x4(ah0, ah1, ah2, ah3, aBase);
            ldmatrix_x4(al0, al1, al2, al3, aBase + 64 * GR_STR);
#pragma unroll
            for (int np = 0; np < 2; np++) {
                uint32_t bBase = smb + 2 * 64 * GR_STR +
                                 (nw * 32 + np * 16 + bRow) * GR_STR + ks * 32 + bKoff;
                uint32_t bh0, bh1, bh2, bh3, bl0, bl1, bl2, bl3;
                ldmatrix_x4(bh0, bh1, bh2, bh3, bBase);
                ldmatrix_x4(bl0, bl1, bl2, bl3, bBase + 64 * GR_STR);
                float* c0 = c[np * 2];
                float* c1 = c[np * 2 + 1];
                mma_bf16(c0, ah0, ah1, ah2, ah3, bh0, bh1);
                mma_bf16(c0, ah0, ah1, ah2, ah3, bl0, bl1);
                mma_bf16(c0, al0, al1, al2, al3, bh0, bh1);
                mma_bf16(c1, ah0, ah1, ah2, ah3, bh2, bh3);
                mma_bf16(c1, ah0, ah1, ah2, ah3, bl2, bl3);
                mma_bf16(c1, al0, al1, al2, al3, bh2, bh3);
            }
        }
    }

    int r0 = row0 + mw * 16 + (lane >> 2);
    int colb = col0 + nw * 32 + (lane & 3) * 2;
#pragma unroll
    for (int nf = 0; nf < 4; nf++) {
        int col = colb + nf * 8;
        if (MODE == 0) {
            *(float2*)(Y + (size_t)r0 * Ee + col) = make_float2(c[nf][0], c[nf][1]);
            *(float2*)(Y + (size_t)(r0 + 8) * Ee + col) = make_float2(c[nf][2], c[nf][3]);
        } else {
            uint32_t h0 = cvt_bf16x2(c[nf][1], c[nf][0]);
            float e0 = __uint_as_float(h0 << 16), e1 = __uint_as_float(h0 & 0xFFFF0000u);
            uint32_t l0 = cvt_bf16x2(c[nf][1] - e1, c[nf][0] - e0);
            uint32_t h1 = cvt_bf16x2(c[nf][3], c[nf][2]);
            float e2 = __uint_as_float(h1 << 16), e3 = __uint_as_float(h1 & 0xFFFF0000u);
            uint32_t l1 = cvt_bf16x2(c[nf][3] - e3, c[nf][2] - e2);
            ((uint32_t*)Yhi)[((size_t)r0 * Ee + col) >> 1] = h0;
            ((uint32_t*)Ylo)[((size_t)r0 * Ee + col) >> 1] = l0;
            ((uint32_t*)Yhi)[((size_t)(r0 + 8) * Ee + col) >> 1] = h1;
            ((uint32_t*)Ylo)[((size_t)(r0 + 8) * Ee + col) >> 1] = l1;
        }
    }
}

// ---------------- K4: softmax denominators ----------------
__global__ __launch_bounds__(256) void stats_kernel(const float* __restrict__ u,
                                                    const float* __restrict__ u_w,
                                                    const float* __restrict__ u_b) {
    int i = blockIdx.x, b = blockIdx.y, t = threadIdx.x;
    __shared__ ull s_w2[48];
    __shared__ ull s_b2[8];
    __shared__ float s_red[8][9];
    if (t < 48) { float w = u_w[t] * LOG2E; s_w2[t] = pack2(w, w); }
    if (t < 8)  { float bb = u_b[t] * LOG2E; s_b2[t] = pack2(bb, bb); }
    __syncthreads();

    int j0 = t * 4;
    unsigned mword = *(const unsigned*)(g_maskT + ((size_t)b * Nn + i) * Nn + j0);
    bool m0 = (mword & 0xFFu) != 0, m1 = ((mword >> 8) & 0xFFu) != 0;
    bool m2 = ((mword >> 16) & 0xFFu) != 0, m3 = ((mword >> 24) & 0xFFu) != 0;

    ulonglong2 u2[Uu];
#pragma unroll
    for (int c = 0; c < Uu; c++)
        u2[c] = *(const ulonglong2*)(u + ((size_t)(b * Uu + c) * Nn + i) * Nn + j0);

    float l[Oo];
#pragma unroll
    for (int o = 0; o < Oo; o++) {
        ull sa = s_b2[o], sb = s_b2[o];
#pragma unroll
        for (int c = 0; c < Uu; c++) {
            sa = ffma2(s_w2[o * Uu + c], u2[c].x, sa);
            sb = ffma2(s_w2[o * Uu + c], u2[c].y, sb);
        }
        float2 f0 = unpack2(sa), f1 = unpack2(sb);
        float acc = 0.f;
        if (!m0) acc += ex2f(f0.x);
        if (!m1) acc += ex2f(f0.y);
        if (!m2) acc += ex2f(f1.x);
        if (!m3) acc += ex2f(f1.y);
        l[o] = acc;
    }
#pragma unroll
    for (int o = 0; o < Oo; o++)
#pragma unroll
        for (int st = 16; st > 0; st >>= 1)
            l[o] += __shfl_xor_sync(0xFFFFFFFFu, l[o], st);
    int w = t >> 5, lane = t & 31;
    if (lane == 0) {
#pragma unroll
        for (int o = 0; o < Oo; o++) s_red[o][w] = l[o];
    }
    __syncthreads();
    if (t < 8) {
        float s = 0.f;
#pragma unroll
        for (int w2 = 0; w2 < 8; w2++) s += s_red[t][w2];
        g_l[((size_t)b * Oo + t) * Nn + i] = s;
    }
}

// ---------------- K5: fused — software-pipelined, double-buffered ----------------
// block = (b, 64-row i strip), 512 threads (16 warps), grid (16, 8); 32 j-tiles of 32.
#define SB_W2    0
#define SB_B2    384
#define SB_BETA  448
#define SB_RL    464          // 512 floats -> ends 2512
#define SB_BUF0  2560
#define BUF_STR  70656        // A: 4*64*144 = 36864 | Vhi: 32*528=16896 | Vlo: 16896
#define BA_OFF   0
#define BVH_OFF  36864
#define BVL_OFF  53760
#define SB_TOT   (2560 + 2 * 70656)   // 143872
#define A_HSTR   9216
#define A_RSTR   144
#define V_RSTR   528

__global__ __launch_bounds__(512, 1) void fused_kernel(const float* __restrict__ u,
                                                       const float* __restrict__ u_w,
                                                       const float* __restrict__ u_b,
                                                       float* __restrict__ attn_out) {
    extern __shared__ char smc[];
    const uint32_t smem_base = smem_u32(smc);
    ull*   s_w2   = (ull*)(smc + SB_W2);
    ull*   s_b2   = (ull*)(smc + SB_B2);
    float* s_beta = (float*)(smc + SB_BETA);
    float* s_rl   = (float*)(smc + SB_RL);

    const int t = threadIdx.x;
    const int wid = t >> 5;
    const int lane = t & 31;
    const int b = blockIdx.y;
    const int i0 = blockIdx.x * 64;

    if (t < 48)      { float w = u_w[t] * LOG2E; s_w2[t] = pack2(w, w); }
    else if (t < 56) { float bb = u_b[t - 48] * LOG2E; s_b2[t - 48] = pack2(bb, bb); }
    else if (t == 56) *s_beta = g_beta;
    {
        int o = t >> 6, il = t & 63;
        s_rl[t] = 1.0f / g_l[((size_t)b * Oo + o) * Nn + i0 + il];
    }
    __syncthreads();

    const float beta = *s_beta;
    // phase A mapping: 1 row x 4 j
    const int jq = t & 7;
    const int il = t >> 3;                 // 0..63
    const int gi = i0 + il;
    // phase B mapping
    const int h_b = wid >> 2;
    const int ig = wid & 3;
    const int lg = lane >> 3, lr = lane & 7;
    const uint32_t a_lm_row = (uint32_t)(ig * 16 + (lg & 1) * 8 + lr);
    const uint32_t a_lm_kh = (uint32_t)(lg >> 1);
    const uint32_t b_lm_krow = (uint32_t)((lg & 1) * 8 + lr);
    const uint32_t b_lm_ncol = (uint32_t)(h_b * 64 + (lg >> 1) * 8);

    float rl[Oo];
#pragma unroll
    for (int o = 0; o < Oo; o++) rl[o] = s_rl[o * 64 + il];

    float c[8][4];
#pragma unroll
    for (int nf = 0; nf < 8; nf++)
#pragma unroll
        for (int k = 0; k < 4; k++) c[nf][k] = 0.f;

    // ---- phase A compute into a buffer (compute scores, write attn gmem + smem) ----
    auto phaseA = [&](int jt, char* buf, const ulonglong2* u2, unsigned mword) {
        const int jg0 = jt * 32 + jq * 4;
        bool m0 = (mword & 0xFFu) != 0, m1 = ((mword >> 8) & 0xFFu) != 0;
        bool m2 = ((mword >> 16) & 0xFFu) != 0, m3 = ((mword >> 24) & 0xFFu) != 0;
        const uint32_t abyte = (uint32_t)(il * A_RSTR + jq * 8);
#pragma unroll
        for (int h = 0; h < Hh; h++) {
            int o0 = 2 * h, o1 = 2 * h + 1;
            ull sa0 = s_b2[o0], sb0 = s_b2[o0];
            ull sa1 = s_b2[o1], sb1 = s_b2[o1];
#pragma unroll
            for (int cc = 0; cc < Uu; cc++) {
                sa0 = ffma2(s_w2[o0 * Uu + cc], u2[cc].x, sa0);
                sb0 = ffma2(s_w2[o0 * Uu + cc], u2[cc].y, sb0);
                sa1 = ffma2(s_w2[o1 * Uu + cc], u2[cc].x, sa1);
                sb1 = ffma2(s_w2[o1 * Uu + cc], u2[cc].y, sb1);
            }
            float2 f00 = unpack2(sa0), f01 = unpack2(sb0);
            float2 f10 = unpack2(sa1), f11 = unpack2(sb1);
            float p00 = m0 ? 0.f : ex2f(f00.x) * rl[o0];
            float p01 = m1 ? 0.f : ex2f(f00.y) * rl[o0];
            float p02 = m2 ? 0.f : ex2f(f01.x) * rl[o0];
            float p03 = m3 ? 0.f : ex2f(f01.y) * rl[o0];
            float p10 = m0 ? 0.f : ex2f(f10.x) * rl[o1];
            float p11 = m1 ? 0.f : ex2f(f10.y) * rl[o1];
            float p12 = m2 ? 0.f : ex2f(f11.x) * rl[o1];
            float p13 = m3 ? 0.f : ex2f(f11.y) * rl[o1];
            float a0 = p00 - beta * p10;
            float a1 = p01 - beta * p11;
            float a2 = p02 - beta * p12;
            float a3 = p03 - beta * p13;
            *(float4*)(attn_out + ((size_t)(b * Hh + h) * Nn + gi) * Nn + jg0) =
                make_float4(a0, a1, a2, a3);
            uint32_t hA = cvt_bf16x2(a1, a0);
            uint32_t hB = cvt_bf16x2(a3, a2);
            float e0 = __uint_as_float(hA << 16);
            float e1 = __uint_as_float(hA & 0xFFFF0000u);
            float e2 = __uint_as_float(hB << 16);
            float e3 = __uint_as_float(hB & 0xFFFF0000u);
            uint32_t lA = cvt_bf16x2(a1 - e1, a0 - e0);
            uint32_t lB = cvt_bf16x2(a3 - e3, a2 - e2);
            char* ap = buf + BA_OFF + h * A_HSTR + abyte;
            *(uint2*)(ap)      = make_uint2(hA, hB);    // hi (64B section)
            *(uint2*)(ap + 64) = make_uint2(lA, lB);    // lo
        }
    };

    // ---- prologue: tile 0 ----
    {
        char* buf0 = smc + SB_BUF0;
        ulonglong2 u2[Uu];
        unsigned mw = *(const unsigned*)(g_maskT + ((size_t)b * Nn + gi) * Nn + jq * 4);
#pragma unroll
        for (int cc = 0; cc < Uu; cc++)
            u2[cc] = *(const ulonglong2*)(u + ((size_t)(b * Uu + cc) * Nn + gi) * Nn + jq * 4);
#pragma unroll
        for (int q = 0; q < 4; q++) {
            int cidx = t + q * 512;
            int isLo = cidx >> 10;
            int r = (cidx >> 5) & 31;
            int k16 = cidx & 31;
            uint4 vv = *(const uint4*)((isLo ? g_v_lo : g_v_hi) +
                                       ((size_t)b * Nn + r) * Ee + k16 * 8);
            *(uint4*)(buf0 + (isLo ? BVL_OFF : BVH_OFF) + r * V_RSTR + k16 * 16) = vv;
        }
        phaseA(0, buf0, u2, mw);
        __syncthreads();
    }

    // ---- pipelined main loop ----
    for (int jt = 0; jt < 32; jt++) {
        char* bufC = smc + SB_BUF0 + (jt & 1) * BUF_STR;
        char* bufN = smc + SB_BUF0 + ((jt + 1) & 1) * BUF_STR;
        const bool has_next = (jt < 31);

        // prefetch LDGs for tile jt+1
        ulonglong2 u2[Uu];
        unsigned mw = 0;
        uint4 vstage[4];
        if (has_next) {
            const int nj0 = (jt + 1) * 32 + jq * 4;
            mw = *(const unsigned*)(g_maskT + ((size_t)b * Nn + gi) * Nn + nj0);
#pragma unroll
            for (int cc = 0; cc < Uu; cc++)
                u2[cc] = *(const ulonglong2*)(u + ((size_t)(b * Uu + cc) * Nn + gi) * Nn + nj0);
#pragma unroll
            for (int q = 0; q < 4; q++) {
                int cidx = t + q * 512;
                int isLo = cidx >> 10;
                int r = (cidx >> 5) & 31;
                int k16 = cidx & 31;
                vstage[q] = *(const uint4*)((isLo ? g_v_lo : g_v_hi) +
                                            ((size_t)b * Nn + (jt + 1) * 32 + r) * Ee + k16 * 8);
            }
        }

        // phase B: MMA from current buffer (tensor pipe; overlaps following FMA work)
        const uint32_t bufC_sm = smem_base + SB_BUF0 + (jt & 1) * BUF_STR;
#pragma unroll
        for (int ks = 0; ks < 2; ks++) {
            uint32_t aAddr = bufC_sm + BA_OFF + h_b * A_HSTR + a_lm_row * A_RSTR +
                             ks * 32 + a_lm_kh * 16;
            uint32_t ah0, ah1, ah2, ah3, al0, al1, al2, al3;
            ldmatrix_x4(ah0, ah1, ah2, ah3, aAddr);
            ldmatrix_x4(al0, al1, al2, al3, aAddr + 64);
#pragma unroll
            for (int np = 0; np < 4; np++) {
                uint32_t bAddr = bufC_sm + BVH_OFF +
                                 (ks * 16 + b_lm_krow) * V_RSTR +
                                 (b_lm_ncol + np * 16) * 2;
                uint32_t bh0, bh1, bh2, bh3, bl0, bl1, bl2, bl3;
                ldmatrix_x4_trans(bh0, bh1, bh2, bh3, bAddr);
                ldmatrix_x4_trans(bl0, bl1, bl2, bl3, bAddr + (BVL_OFF - BVH_OFF));
                float* c0 = c[np * 2];
                float* c1 = c[np * 2 + 1];
                mma_bf16(c0, ah0, ah1, ah2, ah3, bh0, bh1);
                mma_bf16(c0, ah0, ah1, ah2, ah3, bl0, bl1);
                mma_bf16(c0, al0, al1, al2, al3, bh0, bh1);
                mma_bf16(c1, ah0, ah1, ah2, ah3, bh2, bh3);
                mma_bf16(c1, ah0, ah1, ah2, ah3, bl2, bl3);
                mma_bf16(c1, al0, al1, al2, al3, bh2, bh3);
            }
        }

        // store prefetched V + compute phase A for tile jt+1 into next buffer
        if (has_next) {
#pragma unroll
            for (int q = 0; q < 4; q++) {
                int cidx = t + q * 512;
                int isLo = cidx >> 10;
                int r = (cidx >> 5) & 31;
                int k16 = cidx & 31;
                *(uint4*)(bufN + (isLo ? BVL_OFF : BVH_OFF) + r * V_RSTR + k16 * 16) = vstage[q];
            }
            phaseA(jt + 1, bufN, u2, mw);
        }
        __syncthreads();
    }

    // ---- epilogue ----
    {
        int r = lane >> 2, cq = lane & 3;
        int go0 = i0 + ig * 16 + r;
        int go1 = go0 + 8;
#pragma unroll
        for (int nf = 0; nf < 8; nf++) {
            int col = h_b * 64 + nf * 8 + cq * 2;
            uint32_t h0 = cvt_bf16x2(c[nf][1], c[nf][0]);
            float e0 = __uint_as_float(h0 << 16), e1 = __uint_as_float(h0 & 0xFFFF0000u);
            uint32_t l0 = cvt_bf16x2(c[nf][1] - e1, c[nf][0] - e0);
            uint32_t h1 = cvt_bf16x2(c[nf][3], c[nf][2]);
            float e2 = __uint_as_float(h1 << 16), e3 = __uint_as_float(h1 & 0xFFFF0000u);
            uint32_t l1 = cvt_bf16x2(c[nf][3] - e3, c[nf][2] - e2);
            ((uint32_t*)g_op_hi)[(((size_t)b * Nn + go0) * Ee + col) >> 1] = h0;
            ((uint32_t*)g_op_lo)[(((size_t)b * Nn + go0) * Ee + col) >> 1] = l0;
            ((uint32_t*)g_op_hi)[(((size_t)b * Nn + go1) * Ee + col) >> 1] = h1;
            ((uint32_t*)g_op_lo)[(((size_t)b * Nn + go1) * Ee + col) >> 1] = l1;
        }
    }
}

// ---------------- launch ----------------
extern "C" void kernel_launch(void* const* d_in, const int* in_sizes, int n_in,
                              void* d_out, int out_size) {
    const float* x     = (const float*)d_in[0];
    const float* u     = (const float*)d_in[1];
    const void*  umask = d_in[2];
    const float* v_w   = (const float*)d_in[3];
    const float* out_w = (const float*)d_in[4];
    const float* u_w   = (const float*)d_in[5];
    const float* u_b   = (const float*)d_in[6];
    const float* lq    = (const float*)d_in[7];
    const float* lk    = (const float*)d_in[8];

    float* out = (float*)d_out;
    const size_t OUT_ELEMS  = (size_t)Bb * Nn * Ee;
    const size_t ATTN_ELEMS = (size_t)Bb * Hh * Nn * Nn;
    float* attn_out  = out + OUT_ELEMS;
    float* beta_slot = out + OUT_ELEMS + ATTN_ELEMS;

    __nv_bfloat16 *xhi, *xlo, *vwhi, *vwlo, *owhi, *owlo, *vhi, *vlo, *ophi, *oplo;
    cudaGetSymbolAddress((void**)&xhi, g_x_hi);
    cudaGetSymbolAddress((void**)&xlo, g_x_lo);
    cudaGetSymbolAddress((void**)&vwhi, g_vw_hi);
    cudaGetSymbolAddress((void**)&vwlo, g_vw_lo);
    cudaGetSymbolAddress((void**)&owhi, g_ow_hi);
    cudaGetSymbolAddress((void**)&owlo, g_ow_lo);
    cudaGetSymbolAddress((void**)&vhi, g_v_hi);
    cudaGetSymbolAddress((void**)&vlo, g_v_lo);
    cudaGetSymbolAddress((void**)&ophi, g_op_hi);
    cudaGetSymbolAddress((void**)&oplo, g_op_lo);

    static bool attr_set = false;
    if (!attr_set) {
        cudaFuncSetAttribute(fused_kernel, cudaFuncAttributeMaxDynamicSharedMemorySize, SB_TOT);
        attr_set = true;
    }

    detect_beta_kernel<<<1, 256>>>((const unsigned char*)umask, lq, lk, beta_slot);
    mask_transpose_kernel<<<dim3(32, 32, 8), dim3(32, 32)>>>(umask);
    split_all_kernel<<<(NX4 + 2 * NW4 + 255) / 256, 256>>>(x, v_w, out_w);
    gemm_mma_kernel<1><<<dim3(128, 4), 256>>>(xhi, xlo, vwhi, vwlo, nullptr, vhi, vlo);
    stats_kernel<<<dim3(Nn, Bb), 256>>>(u, u_w, u_b);
    fused_kernel<<<dim3(16, 8), 512, SB_TOT>>>(u, u_w, u_b, attn_out);   // launch #6 -> profiled
    gemm_mma_kernel<0><<<dim3(128, 4), 256>>>(ophi, oplo, owhi, owlo, out, nullptr, nullptr);
    (void)in_sizes; (void)n_in; (void)out_size;
}

// round 8
// speedup vs baseline: 1.9856x; 1.1154x over previous
#include <cuda_runtime.h>
#include <cuda_bf16.h>
#include <math.h>
#include <stdint.h>

#define Bb 8
#define Nn 1024
#define Ee 256
#define Hh 4
#define Uu 6
#define Oo 8
#define LAMBDA_INIT 0.63212055882855767840f
#define LOG2E 1.44269504088896340736f

typedef unsigned long long ull;

// ---------------- scratch (static device memory; no allocation) ----------------
__device__ unsigned char g_maskT[(size_t)Bb * Nn * Nn];
__device__ __nv_bfloat16 g_v_hi[(size_t)Bb * Nn * Ee];
__device__ __nv_bfloat16 g_v_lo[(size_t)Bb * Nn * Ee];
__device__ __nv_bfloat16 g_x_hi[(size_t)Bb * Nn * Ee];
__device__ __nv_bfloat16 g_x_lo[(size_t)Bb * Nn * Ee];
__device__ __nv_bfloat16 g_op_hi[(size_t)Bb * Nn * Ee];
__device__ __nv_bfloat16 g_op_lo[(size_t)Bb * Nn * Ee];
__device__ __nv_bfloat16 g_vw_hi[(size_t)Ee * Ee];
__device__ __nv_bfloat16 g_vw_lo[(size_t)Ee * Ee];
__device__ __nv_bfloat16 g_ow_hi[(size_t)Ee * Ee];
__device__ __nv_bfloat16 g_ow_lo[(size_t)Ee * Ee];
__device__ float g_l[(size_t)Bb * Oo * Nn];
__device__ float g_beta;
__device__ int   g_mask_kind;

// ---------------- helpers ----------------
__device__ __forceinline__ ull pack2(float a, float b) {
    ull r; asm("mov.b64 %0, {%1,%2};" : "=l"(r) : "f"(a), "f"(b)); return r;
}
__device__ __forceinline__ ull pack2u(uint32_t a, uint32_t b) {
    ull r; asm("mov.b64 %0, {%1,%2};" : "=l"(r) : "r"(a), "r"(b)); return r;
}
__device__ __forceinline__ float2 unpack2(ull v) {
    float2 r; asm("mov.b64 {%0,%1}, %2;" : "=f"(r.x), "=f"(r.y) : "l"(v)); return r;
}
__device__ __forceinline__ ull ffma2(ull a, ull b, ull c) {
    ull d; asm("fma.rn.f32x2 %0, %1, %2, %3;" : "=l"(d) : "l"(a), "l"(b), "l"(c)); return d;
}
__device__ __forceinline__ uint32_t cvt_bf16x2(float a1, float a0) {
    uint32_t r; asm("cvt.rn.bf16x2.f32 %0, %1, %2;" : "=r"(r) : "f"(a1), "f"(a0)); return r;
}
__device__ __forceinline__ float ex2f(float x) {
    float r; asm("ex2.approx.f32 %0, %1;" : "=f"(r) : "f"(x)); return r;
}
__device__ __forceinline__ uint32_t smem_u32(const void* p) {
    uint32_t a;
    asm("{ .reg .u64 t; cvta.to.shared.u64 t, %1; cvt.u32.u64 %0, t; }" : "=r"(a) : "l"(p));
    return a;
}
__device__ __forceinline__ void ldmatrix_x4(uint32_t& r0, uint32_t& r1, uint32_t& r2,
                                            uint32_t& r3, uint32_t addr) {
    asm volatile("ldmatrix.sync.aligned.m8n8.x4.shared.b16 {%0,%1,%2,%3}, [%4];"
                 : "=r"(r0), "=r"(r1), "=r"(r2), "=r"(r3) : "r"(addr));
}
__device__ __forceinline__ void ldmatrix_x4_trans(uint32_t& r0, uint32_t& r1, uint32_t& r2,
                                                  uint32_t& r3, uint32_t addr) {
    asm volatile("ldmatrix.sync.aligned.m8n8.x4.trans.shared.b16 {%0,%1,%2,%3}, [%4];"
                 : "=r"(r0), "=r"(r1), "=r"(r2), "=r"(r3) : "r"(addr));
}
__device__ __forceinline__ void mma_bf16(float* c, uint32_t a0, uint32_t a1, uint32_t a2,
                                         uint32_t a3, uint32_t b0, uint32_t b1) {
    asm volatile(
        "mma.sync.aligned.m16n8k16.row.col.f32.bf16.bf16.f32 "
        "{%0,%1,%2,%3}, {%4,%5,%6,%7}, {%8,%9}, {%0,%1,%2,%3};"
        : "+f"(c[0]), "+f"(c[1]), "+f"(c[2]), "+f"(c[3])
        : "r"(a0), "r"(a1), "r"(a2), "r"(a3), "r"(b0), "r"(b1));
}

// ---------------- L1: detect mask dtype + beta ----------------
__global__ void detect_beta_kernel(const unsigned char* __restrict__ raw,
                                   const float* __restrict__ lq,
                                   const float* __restrict__ lk,
                                   float* __restrict__ beta_slot) {
    __shared__ int cnt[4];
    __shared__ float red[128];
    int t = threadIdx.x;
    if (t < 4) cnt[t] = 0;
    if (t < 128) red[t] = (t < 100) ? lq[t] * lk[t] : 0.f;
    __syncthreads();
    for (int i = t; i < 16384; i += blockDim.x)
        if (raw[i]) atomicAdd(&cnt[i & 3], 1);
    for (int st = 64; st > 0; st >>= 1) {
        if (t < st) red[t] += red[t + st];
        __syncthreads();
    }
    if (t == 0) {
        int kind;
        if (cnt[1] == 0 && cnt[2] == 0 && cnt[3] == 0) kind = 1;
        else if (cnt[0] == 0 && cnt[1] == 0)           kind = 2;
        else                                            kind = 0;
        g_mask_kind = kind;
        float lam1 = expf(red[0]);
        float beta = 1.f / (1.f + expf(-lam1 * LAMBDA_INIT));
        g_beta = beta;
        *beta_slot = beta;
    }
}

// ---------------- L2: prep = mask transpose (blocks [0,8192)) + splits (rest) ----------------
#define NX4 ((int)((size_t)Bb * Nn * Ee / 4))
#define NW4 (Ee * Ee / 4)
#define PREP_GRID (8192 + (NX4 + 2 * NW4) / 256)

__global__ __launch_bounds__(256) void prep_kernel(const void* __restrict__ rawv,
                                                   const float* __restrict__ x,
                                                   const float* __restrict__ vw,
                                                   const float* __restrict__ ow) {
    int bid = blockIdx.x;
    if (bid < 8192) {
        __shared__ unsigned char tile[32][33];
        int xt = bid & 31, yt = (bid >> 5) & 31, b = bid >> 10;
        int i0 = xt * 32, j0 = yt * 32;
        int tx = threadIdx.x & 31, ty0 = threadIdx.x >> 5;
        int kind = g_mask_kind;
#pragma unroll
        for (int k = 0; k < 4; k++) {
            int ty = ty0 + k * 8;
            size_t src = ((size_t)b * Nn + (j0 + ty)) * Nn + (i0 + tx);
            unsigned char v;
            if (kind == 0)      v = (((const unsigned char*)rawv)[src] != 0);
            else if (kind == 1) v = (((const int*)rawv)[src] != 0);
            else                v = (((const float*)rawv)[src] != 0.f);
            tile[ty][tx] = v;
        }
        __syncthreads();
#pragma unroll
        for (int k = 0; k < 4; k++) {
            int ty = ty0 + k * 8;
            g_maskT[((size_t)b * Nn + (i0 + ty)) * Nn + (j0 + tx)] = tile[tx][ty];
        }
    } else {
        int idx = (bid - 8192) * 256 + threadIdx.x;
        const float* src;
        uint2 *hid, *lod;
        int li;
        if (idx < NX4) {
            src = x; hid = (uint2*)g_x_hi; lod = (uint2*)g_x_lo; li = idx;
        } else if (idx < NX4 + NW4) {
            src = vw; hid = (uint2*)g_vw_hi; lod = (uint2*)g_vw_lo; li = idx - NX4;
        } else {
            src = ow; hid = (uint2*)g_ow_hi; lod = (uint2*)g_ow_lo; li = idx - NX4 - NW4;
        }
        float4 v = ((const float4*)src)[li];
        uint32_t h0 = cvt_bf16x2(v.y, v.x);
        uint32_t h1 = cvt_bf16x2(v.w, v.z);
        float a0 = __uint_as_float(h0 << 16), a1 = __uint_as_float(h0 & 0xFFFF0000u);
        float a2 = __uint_as_float(h1 << 16), a3 = __uint_as_float(h1 & 0xFFFF0000u);
        uint32_t l0 = cvt_bf16x2(v.y - a1, v.x - a0);
        uint32_t l1 = cvt_bf16x2(v.w - a3, v.z - a2);
        hid[li] = make_uint2(h0, h1);
        lod[li] = make_uint2(l0, l1);
    }
}

// ---------------- gemm body (HMMA, 64x64 tile, 3 hi/lo combos) ----------------
#define GR_STR 144
#define GEMM_SMEM (4 * 64 * GR_STR)
template <int MODE>
__device__ __forceinline__ void gemm_body(
    char* sm, int bx, int by,
    const __nv_bfloat16* __restrict__ Ahi, const __nv_bfloat16* __restrict__ Alo,
    const __nv_bfloat16* __restrict__ Whi, const __nv_bfloat16* __restrict__ Wlo,
    float* __restrict__ Y, __nv_bfloat16* __restrict__ Yhi, __nv_bfloat16* __restrict__ Ylo) {
    char* sAh = sm;
    char* sAl = sm + 64 * GR_STR;
    char* sWh = sm + 2 * 64 * GR_STR;
    char* sWl = sm + 3 * 64 * GR_STR;
    const uint32_t smb = smem_u32(sm);

    const int t = threadIdx.x;
    const int wid = t >> 5, lane = t & 31;
    const int row0 = bx * 64;
    const int col0 = by * 64;
    const int mw = wid >> 1, nw = wid & 1;
    const int lr = lane & 7, quad = lane >> 3;
    const uint32_t aRow = (uint32_t)(mw * 16 + (quad & 1) * 8 + lr);
    const uint32_t aKoff = (uint32_t)((quad >> 1) * 16);
    const uint32_t bRow = (uint32_t)((quad >> 1) * 8 + lr);
    const uint32_t bKoff = (uint32_t)((quad & 1) * 16);

    float c[4][4];
#pragma unroll
    for (int nf = 0; nf < 4; nf++)
#pragma unroll
        for (int k = 0; k < 4; k++) c[nf][k] = 0.f;

    for (int kc = 0; kc < 4; kc++) {
        __syncthreads();
#pragma unroll
        for (int q = 0; q < 2; q++) {
            int idx = t + q * 256;
            int r = idx >> 3, c16 = idx & 7;
            *(uint4*)(sAh + r * GR_STR + c16 * 16) =
                ((const uint4*)(Ahi + (size_t)(row0 + r) * Ee + kc * 64))[c16];
            *(uint4*)(sAl + r * GR_STR + c16 * 16) =
                ((const uint4*)(Alo + (size_t)(row0 + r) * Ee + kc * 64))[c16];
            *(uint4*)(sWh + r * GR_STR + c16 * 16) =
                ((const uint4*)(Whi + (size_t)(col0 + r) * Ee + kc * 64))[c16];
            *(uint4*)(sWl + r * GR_STR + c16 * 16) =
                ((const uint4*)(Wlo + (size_t)(col0 + r) * Ee + kc * 64))[c16];
        }
        __syncthreads();
#pragma unroll
        for (int ks = 0; ks < 4; ks++) {
            uint32_t aBase = smb + aRow * GR_STR + ks * 32 + aKoff;
            uint32_t ah0, ah1, ah2, ah3, al0, al1, al2, al3;
            ldmatrix_x4(ah0, ah1, ah2, ah3, aBase);
            ldmatrix_x4(al0, al1, al2, al3, aBase + 64 * GR_STR);
#pragma unroll
            for (int np = 0; np < 2; np++) {
                uint32_t bBase = smb + 2 * 64 * GR_STR +
                                 (nw * 32 + np * 16 + bRow) * GR_STR + ks * 32 + bKoff;
                uint32_t bh0, bh1, bh2, bh3, bl0, bl1, bl2, bl3;
                ldmatrix_x4(bh0, bh1, bh2, bh3, bBase);
                ldmatrix_x4(bl0, bl1, bl2, bl3, bBase + 64 * GR_STR);
                float* c0 = c[np * 2];
                float* c1 = c[np * 2 + 1];
                mma_bf16(c0, ah0, ah1, ah2, ah3, bh0, bh1);
                mma_bf16(c0, ah0, ah1, ah2, ah3, bl0, bl1);
                mma_bf16(c0, al0, al1, al2, al3, bh0, bh1);
                mma_bf16(c1, ah0, ah1, ah2, ah3, bh2, bh3);
                mma_bf16(c1, ah0, ah1, ah2, ah3, bl2, bl3);
                mma_bf16(c1, al0, al1, al2, al3, bh2, bh3);
            }
        }
    }

    int r0 = row0 + mw * 16 + (lane >> 2);
    int colb = col0 + nw * 32 + (lane & 3) * 2;
#pragma unroll
    for (int nf = 0; nf < 4; nf++) {
        int col = colb + nf * 8;
        if (MODE == 0) {
            *(float2*)(Y + (size_t)r0 * Ee + col) = make_float2(c[nf][0], c[nf][1]);
            *(float2*)(Y + (size_t)(r0 + 8) * Ee + col) = make_float2(c[nf][2], c[nf][3]);
        } else {
            uint32_t h0 = cvt_bf16x2(c[nf][1], c[nf][0]);
            float e0 = __uint_as_float(h0 << 16), e1 = __uint_as_float(h0 & 0xFFFF0000u);
            uint32_t l0 = cvt_bf16x2(c[nf][1] - e1, c[nf][0] - e0);
            uint32_t h1 = cvt_bf16x2(c[nf][3], c[nf][2]);
            float e2 = __uint_as_float(h1 << 16), e3 = __uint_as_float(h1 & 0xFFFF0000u);
            uint32_t l1 = cvt_bf16x2(c[nf][3] - e3, c[nf][2] - e2);
            ((uint32_t*)Yhi)[((size_t)r0 * Ee + col) >> 1] = h0;
            ((uint32_t*)Ylo)[((size_t)r0 * Ee + col) >> 1] = l0;
            ((uint32_t*)Yhi)[((size_t)(r0 + 8) * Ee + col) >> 1] = h1;
            ((uint32_t*)Ylo)[((size_t)(r0 + 8) * Ee + col) >> 1] = l1;
        }
    }
}

// ---------------- stats body (softmax denominators) ----------------
__device__ __forceinline__ void stats_body(char* sm, int i, int b,
                                           const float* __restrict__ u,
                                           const float* __restrict__ u_w,
                                           const float* __restrict__ u_b) {
    ull* s_w2 = (ull*)sm;                       // 48 ull
    ull* s_b2 = (ull*)(sm + 384);               // 8 ull
    float* s_red = (float*)(sm + 448);          // 8x9 floats
    int t = threadIdx.x;
    if (t < 48) { float w = u_w[t] * LOG2E; s_w2[t] = pack2(w, w); }
    if (t < 8)  { float bb = u_b[t] * LOG2E; s_b2[t] = pack2(bb, bb); }
    __syncthreads();

    int j0 = t * 4;
    unsigned mword = *(const unsigned*)(g_maskT + ((size_t)b * Nn + i) * Nn + j0);
    bool m0 = (mword & 0xFFu) != 0, m1 = ((mword >> 8) & 0xFFu) != 0;
    bool m2 = ((mword >> 16) & 0xFFu) != 0, m3 = ((mword >> 24) & 0xFFu) != 0;

    ulonglong2 u2[Uu];
#pragma unroll
    for (int c = 0; c < Uu; c++)
        u2[c] = *(const ulonglong2*)(u + ((size_t)(b * Uu + c) * Nn + i) * Nn + j0);

    float l[Oo];
#pragma unroll
    for (int o = 0; o < Oo; o++) {
        ull sa = s_b2[o], sb = s_b2[o];
#pragma unroll
        for (int c = 0; c < Uu; c++) {
            sa = ffma2(s_w2[o * Uu + c], u2[c].x, sa);
            sb = ffma2(s_w2[o * Uu + c], u2[c].y, sb);
        }
        float2 f0 = unpack2(sa), f1 = unpack2(sb);
        float acc = 0.f;
        if (!m0) acc += ex2f(f0.x);
        if (!m1) acc += ex2f(f0.y);
        if (!m2) acc += ex2f(f1.x);
        if (!m3) acc += ex2f(f1.y);
        l[o] = acc;
    }
#pragma unroll
    for (int o = 0; o < Oo; o++)
#pragma unroll
        for (int st = 16; st > 0; st >>= 1)
            l[o] += __shfl_xor_sync(0xFFFFFFFFu, l[o], st);
    int w = t >> 5, lane = t & 31;
    if (lane == 0) {
#pragma unroll
        for (int o = 0; o < Oo; o++) s_red[o * 9 + w] = l[o];
    }
    __syncthreads();
    if (t < 8) {
        float s = 0.f;
#pragma unroll
        for (int w2 = 0; w2 < 8; w2++) s += s_red[t * 9 + w2];
        g_l[((size_t)b * Oo + t) * Nn + i] = s;
    }
}

// ---------------- L3: gemm<1> (blocks [0,512)) + stats (blocks [512, 8704)) ----------------
__global__ __launch_bounds__(256) void gemm1_stats_kernel(const float* __restrict__ u,
                                                          const float* __restrict__ u_w,
                                                          const float* __restrict__ u_b) {
    __shared__ __align__(16) char sm[GEMM_SMEM];
    int bid = blockIdx.x;
    if (bid < 512) {
        gemm_body<1>(sm, bid & 127, bid >> 7,
                     g_x_hi, g_x_lo, g_vw_hi, g_vw_lo, nullptr, g_v_hi, g_v_lo);
    } else {
        int sid = bid - 512;
        stats_body(sm, sid & 1023, sid >> 10, u, u_w, u_b);
    }
}

// ---------------- L5: out projection ----------------
__global__ __launch_bounds__(256) void gemm0_kernel(float* __restrict__ Y) {
    __shared__ __align__(16) char sm[GEMM_SMEM];
    gemm_body<0>(sm, blockIdx.x, blockIdx.y,
                 g_op_hi, g_op_lo, g_ow_hi, g_ow_lo, Y, nullptr, nullptr);
}

// ---------------- L4: fused — software-pipelined, double-buffered ----------------
#define SB_W2    0
#define SB_B2    384
#define SB_BETA  448
#define SB_RL    464
#define SB_BUF0  2560
#define BUF_STR  70656
#define BA_OFF   0
#define BVH_OFF  36864
#define BVL_OFF  53760
#define SB_TOT   (2560 + 2 * 70656)
#define A_HSTR   9216
#define A_RSTR   144
#define V_RSTR   528

__global__ __launch_bounds__(512, 1) void fused_kernel(const float* __restrict__ u,
                                                       const float* __restrict__ u_w,
                                                       const float* __restrict__ u_b,
                                                       float* __restrict__ attn_out) {
    extern __shared__ char smc[];
    const uint32_t smem_base = smem_u32(smc);
    ull*   s_w2   = (ull*)(smc + SB_W2);
    ull*   s_b2   = (ull*)(smc + SB_B2);
    float* s_beta = (float*)(smc + SB_BETA);
    float* s_rl   = (float*)(smc + SB_RL);

    const int t = threadIdx.x;
    const int wid = t >> 5;
    const int lane = t & 31;
    const int b = blockIdx.y;
    const int i0 = blockIdx.x * 64;

    if (t < 48)      { float w = u_w[t] * LOG2E; s_w2[t] = pack2(w, w); }
    else if (t < 56) { float bb = u_b[t - 48] * LOG2E; s_b2[t - 48] = pack2(bb, bb); }
    else if (t == 56) *s_beta = g_beta;
    {
        int o = t >> 6, il = t & 63;
        s_rl[t] = 1.0f / g_l[((size_t)b * Oo + o) * Nn + i0 + il];
    }
    __syncthreads();

    const float beta = *s_beta;
    const int jq = t & 7;
    const int il = t >> 3;
    const int gi = i0 + il;
    const int h_b = wid >> 2;
    const int ig = wid & 3;
    const int lg = lane >> 3, lr = lane & 7;
    const uint32_t a_lm_row = (uint32_t)(ig * 16 + (lg & 1) * 8 + lr);
    const uint32_t a_lm_kh = (uint32_t)(lg >> 1);
    const uint32_t b_lm_krow = (uint32_t)((lg & 1) * 8 + lr);
    const uint32_t b_lm_ncol = (uint32_t)(h_b * 64 + (lg >> 1) * 8);

    float rl[Oo];
#pragma unroll
    for (int o = 0; o < Oo; o++) rl[o] = s_rl[o * 64 + il];

    float c[8][4];
#pragma unroll
    for (int nf = 0; nf < 8; nf++)
#pragma unroll
        for (int k = 0; k < 4; k++) c[nf][k] = 0.f;

    auto load_u = [&](int jg0, ulonglong2* u2, unsigned& mw) {
        mw = __ldcs((const unsigned*)(g_maskT + ((size_t)b * Nn + gi) * Nn + jg0));
#pragma unroll
        for (int cc = 0; cc < Uu; cc++) {
            uint4 raw = __ldcs((const uint4*)(u + ((size_t)(b * Uu + cc) * Nn + gi) * Nn + jg0));
            u2[cc].x = pack2u(raw.x, raw.y);
            u2[cc].y = pack2u(raw.z, raw.w);
        }
    };

    auto phaseA = [&](int jt, char* buf, const ulonglong2* u2, unsigned mword) {
        const int jg0 = jt * 32 + jq * 4;
        bool m0 = (mword & 0xFFu) != 0, m1 = ((mword >> 8) & 0xFFu) != 0;
        bool m2 = ((mword >> 16) & 0xFFu) != 0, m3 = ((mword >> 24) & 0xFFu) != 0;
        const uint32_t abyte = (uint32_t)(il * A_RSTR + jq * 8);
#pragma unroll
        for (int h = 0; h < Hh; h++) {
            int o0 = 2 * h, o1 = 2 * h + 1;
            ull sa0 = s_b2[o0], sb0 = s_b2[o0];
            ull sa1 = s_b2[o1], sb1 = s_b2[o1];
#pragma unroll
            for (int cc = 0; cc < Uu; cc++) {
                sa0 = ffma2(s_w2[o0 * Uu + cc], u2[cc].x, sa0);
                sb0 = ffma2(s_w2[o0 * Uu + cc], u2[cc].y, sb0);
                sa1 = ffma2(s_w2[o1 * Uu + cc], u2[cc].x, sa1);
                sb1 = ffma2(s_w2[o1 * Uu + cc], u2[cc].y, sb1);
            }
            float2 f00 = unpack2(sa0), f01 = unpack2(sb0);
            float2 f10 = unpack2(sa1), f11 = unpack2(sb1);
            float p00 = m0 ? 0.f : ex2f(f00.x) * rl[o0];
            float p01 = m1 ? 0.f : ex2f(f00.y) * rl[o0];
            float p02 = m2 ? 0.f : ex2f(f01.x) * rl[o0];
            float p03 = m3 ? 0.f : ex2f(f01.y) * rl[o0];
            float p10 = m0 ? 0.f : ex2f(f10.x) * rl[o1];
            float p11 = m1 ? 0.f : ex2f(f10.y) * rl[o1];
            float p12 = m2 ? 0.f : ex2f(f11.x) * rl[o1];
            float p13 = m3 ? 0.f : ex2f(f11.y) * rl[o1];
            float a0 = p00 - beta * p10;
            float a1 = p01 - beta * p11;
            float a2 = p02 - beta * p12;
            float a3 = p03 - beta * p13;
            __stcs((float4*)(attn_out + ((size_t)(b * Hh + h) * Nn + gi) * Nn + jg0),
                   make_float4(a0, a1, a2, a3));
            uint32_t hA = cvt_bf16x2(a1, a0);
            uint32_t hB = cvt_bf16x2(a3, a2);
            float e0 = __uint_as_float(hA << 16);
            float e1 = __uint_as_float(hA & 0xFFFF0000u);
            float e2 = __uint_as_float(hB << 16);
            float e3 = __uint_as_float(hB & 0xFFFF0000u);
            uint32_t lA = cvt_bf16x2(a1 - e1, a0 - e0);
            uint32_t lB = cvt_bf16x2(a3 - e3, a2 - e2);
            char* ap = buf + BA_OFF + h * A_HSTR + abyte;
            *(uint2*)(ap)      = make_uint2(hA, hB);
            *(uint2*)(ap + 64) = make_uint2(lA, lB);
        }
    };

    // ---- prologue: tile 0 ----
    {
        char* buf0 = smc + SB_BUF0;
        ulonglong2 u2[Uu];
        unsigned mw;
        load_u(jq * 4, u2, mw);
#pragma unroll
        for (int q = 0; q < 4; q++) {
            int cidx = t + q * 512;
            int isLo = cidx >> 10;
            int r = (cidx >> 5) & 31;
            int k16 = cidx & 31;
            uint4 vv = *(const uint4*)((isLo ? g_v_lo : g_v_hi) +
                                       ((size_t)b * Nn + r) * Ee + k16 * 8);
            *(uint4*)(buf0 + (isLo ? BVL_OFF : BVH_OFF) + r * V_RSTR + k16 * 16) = vv;
        }
        phaseA(0, buf0, u2, mw);
        __syncthreads();
    }

    // ---- pipelined main loop ----
    for (int jt = 0; jt < 32; jt++) {
        char* bufN = smc + SB_BUF0 + ((jt + 1) & 1) * BUF_STR;
        const bool has_next = (jt < 31);

        ulonglong2 u2[Uu];
        unsigned mw = 0;
        uint4 vstage[4];
        if (has_next) {
            load_u((jt + 1) * 32 + jq * 4, u2, mw);
#pragma unroll
            for (int q = 0; q < 4; q++) {
                int cidx = t + q * 512;
                int isLo = cidx >> 10;
                int r = (cidx >> 5) & 31;
                int k16 = cidx & 31;
                vstage[q] = *(const uint4*)((isLo ? g_v_lo : g_v_hi) +
                                            ((size_t)b * Nn + (jt + 1) * 32 + r) * Ee + k16 * 8);
            }
        }

        const uint32_t bufC_sm = smem_base + SB_BUF0 + (jt & 1) * BUF_STR;
#pragma unroll
        for (int ks = 0; ks < 2; ks++) {
            uint32_t aAddr = bufC_sm + BA_OFF + h_b * A_HSTR + a_lm_row * A_RSTR +
                             ks * 32 + a_lm_kh * 16;
            uint32_t ah0, ah1, ah2, ah3, al0, al1, al2, al3;
            ldmatrix_x4(ah0, ah1, ah2, ah3, aAddr);
            ldmatrix_x4(al0, al1, al2, al3, aAddr + 64);
#pragma unroll
            for (int np = 0; np < 4; np++) {
                uint32_t bAddr = bufC_sm + BVH_OFF +
                                 (ks * 16 + b_lm_krow) * V_RSTR +
                                 (b_lm_ncol + np * 16) * 2;
                uint32_t bh0, bh1, bh2, bh3, bl0, bl1, bl2, bl3;
                ldmatrix_x4_trans(bh0, bh1, bh2, bh3, bAddr);
                ldmatrix_x4_trans(bl0, bl1, bl2, bl3, bAddr + (BVL_OFF - BVH_OFF));
                float* c0 = c[np * 2];
                float* c1 = c[np * 2 + 1];
                mma_bf16(c0, ah0, ah1, ah2, ah3, bh0, bh1);
                mma_bf16(c0, ah0, ah1, ah2, ah3, bl0, bl1);
                mma_bf16(c0, al0, al1, al2, al3, bh0, bh1);
                mma_bf16(c1, ah0, ah1, ah2, ah3, bh2, bh3);
                mma_bf16(c1, ah0, ah1, ah2, ah3, bl2, bl3);
                mma_bf16(c1, al0, al1, al2, al3, bh2, bh3);
            }
        }

        if (has_next) {
#pragma unroll
            for (int q = 0; q < 4; q++) {
                int cidx = t + q * 512;
                int isLo = cidx >> 10;
                int r = (cidx >> 5) & 31;
                int k16 = cidx & 31;
                *(uint4*)(bufN + (isLo ? BVL_OFF : BVH_OFF) + r * V_RSTR + k16 * 16) = vstage[q];
            }
            phaseA(jt + 1, bufN, u2, mw);
        }
        __syncthreads();
    }

    // ---- epilogue ----
    {
        int r = lane >> 2, cq = lane & 3;
        int go0 = i0 + ig * 16 + r;
        int go1 = go0 + 8;
#pragma unroll
        for (int nf = 0; nf < 8; nf++) {
            int col = h_b * 64 + nf * 8 + cq * 2;
            uint32_t h0 = cvt_bf16x2(c[nf][1], c[nf][0]);
            float e0 = __uint_as_float(h0 << 16), e1 = __uint_as_float(h0 & 0xFFFF0000u);
            uint32_t l0 = cvt_bf16x2(c[nf][1] - e1, c[nf][0] - e0);
            uint32_t h1 = cvt_bf16x2(c[nf][3], c[nf][2]);
            float e2 = __uint_as_float(h1 << 16), e3 = __uint_as_float(h1 & 0xFFFF0000u);
            uint32_t l1 = cvt_bf16x2(c[nf][3] - e3, c[nf][2] - e2);
            ((uint32_t*)g_op_hi)[(((size_t)b * Nn + go0) * Ee + col) >> 1] = h0;
            ((uint32_t*)g_op_lo)[(((size_t)b * Nn + go0) * Ee + col) >> 1] = l0;
            ((uint32_t*)g_op_hi)[(((size_t)b * Nn + go1) * Ee + col) >> 1] = h1;
            ((uint32_t*)g_op_lo)[(((size_t)b * Nn + go1) * Ee + col) >> 1] = l1;
        }
    }
}

// ---------------- launch ----------------
extern "C" void kernel_launch(void* const* d_in, const int* in_sizes, int n_in,
                              void* d_out, int out_size) {
    const float* x     = (const float*)d_in[0];
    const float* u     = (const float*)d_in[1];
    const void*  umask = d_in[2];
    const float* v_w   = (const float*)d_in[3];
    const float* out_w = (const float*)d_in[4];
    const float* u_w   = (const float*)d_in[5];
    const float* u_b   = (const float*)d_in[6];
    const float* lq    = (const float*)d_in[7];
    const float* lk    = (const float*)d_in[8];

    float* out = (float*)d_out;
    const size_t OUT_ELEMS  = (size_t)Bb * Nn * Ee;
    const size_t ATTN_ELEMS = (size_t)Bb * Hh * Nn * Nn;
    float* attn_out  = out + OUT_ELEMS;
    float* beta_slot = out + OUT_ELEMS + ATTN_ELEMS;

    static bool attr_set = false;
    if (!attr_set) {
        cudaFuncSetAttribute(fused_kernel, cudaFuncAttributeMaxDynamicSharedMemorySize, SB_TOT);
        attr_set = true;
    }

    detect_beta_kernel<<<1, 256>>>((const unsigned char*)umask, lq, lk, beta_slot);  // #1
    prep_kernel<<<PREP_GRID, 256>>>(umask, x, v_w, out_w);                            // #2
    gemm1_stats_kernel<<<512 + Nn * Bb, 256>>>(u, u_w, u_b);                          // #3
    fused_kernel<<<dim3(16, 8), 512, SB_TOT>>>(u, u_w, u_b, attn_out);                // #4 (profiled)
    gemm0_kernel<<<dim3(128, 4), 256>>>(out);                                         // #5
    (void)in_sizes; (void)n_in; (void)out_size;
}